// round 11
// baseline (speedup 1.0000x reference)
#include <cuda_runtime.h>
#include <cuda_fp16.h>
#include <math.h>
#include <stddef.h>
#include <stdint.h>

#define NB 4
#define NC 128
#define NCO 256
#define NH 96
#define NW 96
#define NHW (NH*NW)          // 9216
#define NKK 9
#define NKDIM (NKK*NC)       // 1152

// ---- scratch (static device allocations) ----
__device__ __half  g_xh[(size_t)NB*NHW*NC];     // x as NHWC fp16 (9.4 MB)
__device__ __half2 g_wAf[36*4096];              // main weights, FRAGMENT order
__device__ __half2 g_w27h[72*8*32];             // conv27 weights [k2 global][ch]
__device__ float   g_meta[(size_t)NB*NKK*NHW*8];// per (b,kk,px): 4 weights + 4 indices

static __device__ __forceinline__ unsigned su32(const void* p){
    return (unsigned)__cvta_generic_to_shared(p);
}
static __device__ __forceinline__ void mma_f16(float* c, const uint32_t* a, const uint32_t* b){
    asm volatile("mma.sync.aligned.m16n8k16.row.col.f32.f16.f16.f32 "
        "{%0,%1,%2,%3}, {%4,%5,%6,%7}, {%8,%9}, {%0,%1,%2,%3};"
        : "+f"(c[0]), "+f"(c[1]), "+f"(c[2]), "+f"(c[3])
        : "r"(a[0]), "r"(a[1]), "r"(a[2]), "r"(a[3]), "r"(b[0]), "r"(b[1]));
}
static __device__ __forceinline__ void cpa_wait1(){
    asm volatile("cp.async.wait_group 1;\n" ::: "memory");
}
static __device__ __forceinline__ void cpa_wait0(){
    asm volatile("cp.async.wait_group 0;\n" ::: "memory");
}

// ---------------- transpose x: NCHW fp32 -> NHWC fp16 ----------------
__global__ void k_transpose(const float* __restrict__ x){
    __shared__ float tile[32][33];
    int b = blockIdx.z, c0 = blockIdx.y*32, p0 = blockIdx.x*32;
    int tx = threadIdx.x, ty = threadIdx.y;
    int t = ty*32 + tx;
#pragma unroll
    for (int i = ty; i < 32; i += 8)
        tile[i][tx] = x[((size_t)(b*NC + c0 + i))*NHW + p0 + tx];
    __syncthreads();
#pragma unroll
    for (int it = 0; it < 2; it++){
        int idx = it*256 + t;
        int p = idx >> 4, q = idx & 15;
        __half2 h = __floats2half2_rn(tile[2*q][p], tile[2*q+1][p]);
        *(__half2*)&g_xh[(size_t)(b*NHW + p0 + p)*NC + c0 + 2*q] = h;
    }
}

// ---------------- weight prep: fragment-order for main GEMM ----------------
__global__ void k_prep_wAf(const float* __restrict__ w){
    int idx = blockIdx.x*256 + threadIdx.x;
    if (idx >= 36*4096) return;
    int chunk = idx >> 12;
    int rem   = idx & 4095;
    int ks    = rem >> 11;
    int mtg   = (rem >> 7) & 15;
    int lane  = (rem >> 2) & 31;
    int r     = rem & 3;
    int acol = lane & 3, arow = lane >> 2;
    int k2 = chunk*16 + ks*8 + acol + ((r>>1)<<2);
    int co = mtg*16 + arow + ((r&1)<<3);
    int k = 2*k2;
    int kk = k >> 7, c = k & 127;
    float w0 = w[(size_t)(co*NC + c)*NKK + kk];
    float w1 = w[(size_t)(co*NC + c + 1)*NKK + kk];
    g_wAf[idx] = __floats2half2_rn(w0, w1);
}

__global__ void k_prep_w27h(const float* __restrict__ ow, const float* __restrict__ mw){
    int idx = blockIdx.x*256 + threadIdx.x;
    if (idx >= 72*8*32) return;
    int ch = idx & 31, r = idx >> 5;
    int stage = r >> 3, k2 = r & 7;
    int k = stage*16 + 2*k2;
    int kk = k >> 7, c = k & 127;
    float v0 = 0.f, v1 = 0.f;
    if (ch < 18){      v0 = ow[(size_t)(ch*NC + c)*NKK + kk];
                       v1 = ow[(size_t)(ch*NC + c + 1)*NKK + kk]; }
    else if (ch < 27){ v0 = mw[(size_t)((ch-18)*NC + c)*NKK + kk];
                       v1 = mw[(size_t)((ch-18)*NC + c + 1)*NKK + kk]; }
    g_w27h[idx] = __floats2half2_rn(v0, v1);
}

// ---------------- conv27 (offsets + modulation) fp16 mma + meta build ------
// Block: 128 px x 32 ch. 256 threads, 8 warps x (32ch x 16px). 36 K32 stages.
// 3-stage A pipeline (wait_group 1), 2-stage B (register-held).
#define C_AS 40
#define C_BS 136
#define OPAD 130
__global__ __launch_bounds__(256,2) void k_conv27(const float* __restrict__ off_b,
                                                  const float* __restrict__ mod_b){
    __shared__ __half2 A2c[3][16*C_AS];
    __shared__ __half2 B2c[2][16*C_BS];
    __shared__ float sOut[32][OPAD];

    const int b = blockIdx.y, p0 = blockIdx.x*128;
    const int t = threadIdx.x;
    const int wid = t>>5, lane = t&31;
    const int bpx = t>>2, bcq = t&3;
    const int arow = lane>>2, acol = lane&3;
    const int wn = wid*16;
    const __half* __restrict__ xb = g_xh + (size_t)b*NHW*NC;

    const __half* gp0 = xb; const __half* gp1 = xb;
    bool v0=false, v1=false;
    uint4 r0, r1;

    float acc[2][2][4];
#pragma unroll
    for (int i=0;i<2;i++)
#pragma unroll
        for (int j=0;j<2;j++)
#pragma unroll
            for (int q=0;q<4;q++) acc[i][j][q]=0.f;

    auto geom = [&](int kk){
        int ky = kk/3, kx = kk - ky*3;
#pragma unroll
        for (int i=0;i<2;i++){
            int p = p0 + bpx + 64*i;
            int h = p/96, w = p - h*96;
            int sy = h - 1 + ky, sx = w - 1 + kx;
            bool v = ((unsigned)sy < 96u) && ((unsigned)sx < 96u);
            const __half* gp = xb + (ptrdiff_t)(sy*96 + sx)*NC;
            if (i==0){ v0=v; gp0=gp; } else { v1=v; gp1=gp; }
        }
    };
    auto issue_a = [&](int s, int buf){
        if (t < 128){
            int row = t>>3, seg = t&7;                 // 16 rows x 8 segs(16B)
            unsigned d = su32(&A2c[buf][row*C_AS + seg*4]);
            const __half2* src = g_w27h + (size_t)(s*16 + row)*32 + seg*4;
            asm volatile("cp.async.cg.shared.global [%0], [%1], 16;\n" :: "r"(d), "l"(src));
        }
        asm volatile("cp.async.commit_group;\n");
    };
    auto issue_b = [&](int s){
        int c = (s&3)*32 + (bcq<<3);
        r0 = make_uint4(0u,0u,0u,0u);
        r1 = make_uint4(0u,0u,0u,0u);
        if (v0) r0 = *(const uint4*)(gp0 + c);
        if (v1) r1 = *(const uint4*)(gp1 + c);
    };
    auto store_b = [&](int buf){
        int xr = bcq<<3;
        const uint32_t* w0 = &r0.x;
        const uint32_t* w1 = &r1.x;
#pragma unroll
        for (int j=0;j<4;j++){
            int k2 = 4*bcq + j;
            *(uint32_t*)&B2c[buf][k2*C_BS + (bpx ^ xr)] = w0[j];
            *(uint32_t*)&B2c[buf][k2*C_BS + ((bpx+64) ^ xr)] = w1[j];
        }
    };

    geom(0);
    issue_a(0,0); issue_a(1,1);
    issue_b(0); store_b(0);
    cpa_wait1();
    __syncthreads();

    for (int s=0;s<36;s++){
        if (s<34) issue_a(s+2, (s+2)%3);
        if (s<35){
            if (((s+1)&3)==0) geom((s+1)>>2);
            issue_b(s+1);
        }
        const __half2* Ab = A2c[s%3];
        const __half2* Bb = B2c[s&1];
#pragma unroll
        for (int ks=0; ks<2; ks++){
            uint32_t a[2][4];
#pragma unroll
            for (int mt=0;mt<2;mt++){
                a[mt][0] = *(const uint32_t*)&Ab[(ks*8+acol)*C_AS + 16*mt + arow];
                a[mt][1] = *(const uint32_t*)&Ab[(ks*8+acol)*C_AS + 16*mt + arow + 8];
                a[mt][2] = *(const uint32_t*)&Ab[(ks*8+acol+4)*C_AS + 16*mt + arow];
                a[mt][3] = *(const uint32_t*)&Ab[(ks*8+acol+4)*C_AS + 16*mt + arow + 8];
            }
            int xr0 = ((ks*8+acol)>>2)<<3;
            int xr1 = ((ks*8+acol+4)>>2)<<3;
            uint32_t bq[2][2];
#pragma unroll
            for (int nt=0;nt<2;nt++){
                int pxn = wn + 8*nt + arow;
                bq[nt][0] = *(const uint32_t*)&Bb[(ks*8+acol)*C_BS + (pxn ^ xr0)];
                bq[nt][1] = *(const uint32_t*)&Bb[(ks*8+acol+4)*C_BS + (pxn ^ xr1)];
            }
#pragma unroll
            for (int mt=0;mt<2;mt++)
#pragma unroll
                for (int nt=0;nt<2;nt++)
                    mma_f16(acc[mt][nt], a[mt], bq[nt]);
        }

        if (s<35) store_b((s&1)^1);
        if (s<34) cpa_wait1();
        else if (s==34) cpa_wait0();
        __syncthreads();
    }

    // write conv output fragments to sOut
#pragma unroll
    for (int mt=0;mt<2;mt++)
#pragma unroll
        for (int nt=0;nt<2;nt++){
            int row = 16*mt + arow;
            int col = wn + 8*nt + 2*acol;
            float* cp = &sOut[row][col];
            cp[0] = acc[mt][nt][0]; cp[1] = acc[mt][nt][1];
            cp[8*OPAD] = acc[mt][nt][2]; cp[8*OPAD+1] = acc[mt][nt][3];
        }
    __syncthreads();

    if (t < 128){
        int p = p0 + t;
        int h = p/96, w = p - h*96;
#pragma unroll
        for (int kk=0; kk<9; kk++){
            float dy = sOut[2*kk  ][t] + off_b[2*kk];
            float dx = sOut[2*kk+1][t] + off_b[2*kk+1];
            float mp = sOut[18+kk][t] + mod_b[kk];
            float m  = 1.f/(1.f + expf(-mp));
            int ky = kk/3, kx = kk - ky*3;
            float py  = (float)(h - 1 + ky) + dy;
            float pxf = (float)(w - 1 + kx) + dx;
            float fy = floorf(py), fx = floorf(pxf);
            float ly = py - fy,  lx = pxf - fx;
            int y0 = (int)fy, x0 = (int)fx;
            int y1 = y0+1,   x1 = x0+1;
            bool vy0 = (unsigned)y0 < 96u, vy1 = (unsigned)y1 < 96u;
            bool vx0 = (unsigned)x0 < 96u, vx1 = (unsigned)x1 < 96u;
            float hy = 1.f - ly, hx = 1.f - lx;
            float w00 = (vy0&&vx0) ? hy*hx*m : 0.f;
            float w01 = (vy0&&vx1) ? hy*lx*m : 0.f;
            float w10 = (vy1&&vx0) ? ly*hx*m : 0.f;
            float w11 = (vy1&&vx1) ? ly*lx*m : 0.f;
            int cy0 = min(max(y0,0),95), cy1 = min(max(y1,0),95);
            int cx0 = min(max(x0,0),95), cx1 = min(max(x1,0),95);
            int i00 = (cy0*96+cx0)*NC, i01 = (cy0*96+cx1)*NC;
            int i10 = (cy1*96+cx0)*NC, i11 = (cy1*96+cx1)*NC;
            float* mo = &g_meta[((size_t)(b*NKK+kk)*NHW + p)*8];
            *(float4*)mo = make_float4(w00,w01,w10,w11);
            *(float4*)(mo+4) = make_float4(__int_as_float(i00), __int_as_float(i01),
                                           __int_as_float(i10), __int_as_float(i11));
        }
    }
}

// ---------------- main fused deformable GEMM: mma.sync fp16 ----------------
// Block tile: 256co x 128px, K=1152 in 36 chunks of 32 (16 k2 rows).
// 256 threads, 8 warps (4m x 2n), warp tile 64co x 64px.
// A: fragment-order smem (LDS.128), 3-stage cp.async pipeline (wait_group 1).
// B: swizzled [k2][px] smem, 2-stage register-held.
#define CHUNKS 36
#define A2H2 4096                 // half2 per A buffer
#define B2S 136
#define B2BUF (16*B2S)            // 2176 half2
#define SMEM_PIPE_BYTES ((3*A2H2 + 2*B2BUF)*4)   // 66560
#define SMEM_EPI_BYTES (128*132*4)               // 67584

__global__ __launch_bounds__(256,1) void k_main_mma(const float* __restrict__ bias,
                                                    float* __restrict__ out){
    extern __shared__ char smraw[];
    __half2* A2 = (__half2*)smraw;              // [3][4096] fragment order
    __half2* B2 = A2 + 3*A2H2;                  // [2][16][B2S]
    float*   Cs = (float*)smraw;                // epilogue [128][132]

    const int t = threadIdx.x;
    const int wid = t>>5, lane = t&31;
    const int b = blockIdx.y, p0 = blockIdx.x*128;
    const __half* __restrict__ xb = g_xh + (size_t)b*NHW*NC;

    const int pxb = t>>2, q = t&3;
    const int wm4 = (wid&3)*4, wn = (wid>>2)*64;
    const int arow = lane>>2, acol = lane&3;

    float4 mw0 = make_float4(0,0,0,0), mw1 = make_float4(0,0,0,0);
    int4 mi0 = make_int4(0,0,0,0), mi1 = make_int4(0,0,0,0);
    __half2 rg[2][4];

    float acc[4][8][4];
#pragma unroll
    for (int i=0;i<4;i++)
#pragma unroll
        for (int j=0;j<8;j++)
#pragma unroll
            for (int qq=0;qq<4;qq++) acc[i][j][qq]=0.f;

    auto load_meta = [&](int kk){
        const float4* mp0 = (const float4*)&g_meta[((size_t)(b*NKK+kk)*NHW + p0 + pxb)*8];
        mw0 = mp0[0];
        float4 ti = mp0[1];
        mi0.x = __float_as_int(ti.x); mi0.y = __float_as_int(ti.y);
        mi0.z = __float_as_int(ti.z); mi0.w = __float_as_int(ti.w);
        const float4* mp1 = (const float4*)&g_meta[((size_t)(b*NKK+kk)*NHW + p0 + pxb + 64)*8];
        mw1 = mp1[0];
        float4 tj = mp1[1];
        mi1.x = __float_as_int(tj.x); mi1.y = __float_as_int(tj.y);
        mi1.z = __float_as_int(tj.z); mi1.w = __float_as_int(tj.w);
    };
    auto issue_a = [&](int chunk, int buf){
#pragma unroll
        for (int i=0;i<4;i++){
            int qq = t + 256*i;               // 0..1023, 16B each -> 16KB linear
            const __half2* src = g_wAf + (size_t)chunk*4096 + qq*4;
            unsigned dst = su32(A2 + buf*A2H2 + qq*4);
            asm volatile("cp.async.cg.shared.global [%0], [%1], 16;\n" :: "r"(dst), "l"(src));
        }
        asm volatile("cp.async.commit_group;\n");
    };
    auto gather = [&](int chunk){
        int csub = (chunk&3)*32 + q*8;
#pragma unroll
        for (int e=0;e<2;e++){
            const int4 mi = e ? mi1 : mi0;
            const float4 mwv = e ? mw1 : mw0;
            uint4 u0 = *(const uint4*)(xb + mi.x + csub);
            uint4 u1 = *(const uint4*)(xb + mi.y + csub);
            uint4 u2 = *(const uint4*)(xb + mi.z + csub);
            uint4 u3 = *(const uint4*)(xb + mi.w + csub);
            const uint32_t* p0v = &u0.x;
            const uint32_t* p1v = &u1.x;
            const uint32_t* p2v = &u2.x;
            const uint32_t* p3v = &u3.x;
#pragma unroll
            for (int j=0;j<4;j++){
                float2 f0 = __half22float2(*(const __half2*)&p0v[j]);
                float2 f1 = __half22float2(*(const __half2*)&p1v[j]);
                float2 f2 = __half22float2(*(const __half2*)&p2v[j]);
                float2 f3 = __half22float2(*(const __half2*)&p3v[j]);
                float vx = mwv.x*f0.x + mwv.y*f1.x + mwv.z*f2.x + mwv.w*f3.x;
                float vy = mwv.x*f0.y + mwv.y*f1.y + mwv.z*f2.y + mwv.w*f3.y;
                rg[e][j] = __floats2half2_rn(vx, vy);
            }
        }
    };
    auto store_b = [&](int buf){
        int xr = ((q>>1)<<4) ^ ((q&1)<<3);
#pragma unroll
        for (int j=0;j<4;j++){
            int k2 = q*4 + j;
            B2[buf*B2BUF + k2*B2S + (pxb ^ xr)] = rg[0][j];
            B2[buf*B2BUF + k2*B2S + ((pxb+64) ^ xr)] = rg[1][j];
        }
    };

    load_meta(0);
    issue_a(0, 0); issue_a(1, 1);
    gather(0);
    store_b(0);
    cpa_wait1();
    __syncthreads();

    for (int chunk=0; chunk<CHUNKS; chunk++){
        if (chunk < 34) issue_a(chunk+2, (chunk+2)%3);
        if (chunk < 35){
            if (((chunk+1)&3)==0) load_meta((chunk+1)>>2);
            gather(chunk+1);
        }

        const __half2* Ab = A2 + (chunk%3)*A2H2;
        const __half2* Bb = B2 + (chunk&1)*B2BUF;
#pragma unroll
        for (int ks=0; ks<2; ks++){
            uint32_t a[4][4];
#pragma unroll
            for (int mt=0;mt<4;mt++){
                uint4 av = *(const uint4*)(Ab + (ks*16 + wm4 + mt)*128 + lane*4);
                a[mt][0] = av.x; a[mt][1] = av.y; a[mt][2] = av.z; a[mt][3] = av.w;
            }
            uint32_t bq[8][2];
#pragma unroll
            for (int nt=0;nt<8;nt++){
                int pxn = (wn + 8*nt + arow) ^ (ks<<4);
                bq[nt][0] = *(const uint32_t*)&Bb[(ks*8+acol)*B2S + pxn];
                bq[nt][1] = *(const uint32_t*)&Bb[(ks*8+acol+4)*B2S + (pxn^8)];
            }
#pragma unroll
            for (int mt=0;mt<4;mt++)
#pragma unroll
                for (int nt=0;nt<8;nt++)
                    mma_f16(acc[mt][nt], a[mt], bq[nt]);
        }

        if (chunk < 35) store_b((chunk&1)^1);
        if (chunk < 34) cpa_wait1();
        else if (chunk == 34) cpa_wait0();
        __syncthreads();
    }

    // ---- epilogue: stage C through smem in 2 co-halves, coalesced + bias ----
#pragma unroll
    for (int h=0; h<2; h++){
        __syncthreads();
        if (((wid&3)>>1) == h){
            int rbase = (wid&3)*64 - 128*h;   // 0 or 64
#pragma unroll
            for (int mt=0;mt<4;mt++){
#pragma unroll
                for (int nt=0;nt<8;nt++){
                    int row = rbase + 16*mt + arow;
                    int col = wn + nt*8 + 2*acol;
                    float* cp2 = Cs + row*132 + col;
                    cp2[0] = acc[mt][nt][0]; cp2[1] = acc[mt][nt][1];
                    cp2[8*132] = acc[mt][nt][2]; cp2[8*132+1] = acc[mt][nt][3];
                }
            }
        }
        __syncthreads();
        {
            int r = t>>1, seg = (t&1)*64;
            int co = 128*h + r;
            float bz = __ldg(&bias[co]);
            float* op = out + (size_t)(b*NCO + co)*NHW + p0 + seg;
            const float* cr = Cs + r*132 + seg;
#pragma unroll
            for (int j=0;j<16;j++){
                float4 v = *(const float4*)(cr + j*4);
                v.x += bz; v.y += bz; v.z += bz; v.w += bz;
                *(float4*)(op + j*4) = v;
            }
        }
    }
}

// ---------------- launch ----------------
extern "C" void kernel_launch(void* const* d_in, const int* in_sizes, int n_in,
                              void* d_out, int out_size){
    (void)in_sizes; (void)n_in; (void)out_size;
    const float* x        = (const float*)d_in[0];
    const float* weight   = (const float*)d_in[1];
    const float* bias     = (const float*)d_in[2];
    const float* offset_w = (const float*)d_in[3];
    const float* offset_b = (const float*)d_in[4];
    const float* mod_w    = (const float*)d_in[5];
    const float* mod_b    = (const float*)d_in[6];
    float* out = (float*)d_out;

    const int SMEM_MAIN = (SMEM_PIPE_BYTES > SMEM_EPI_BYTES) ? SMEM_PIPE_BYTES : SMEM_EPI_BYTES;
    cudaFuncSetAttribute(k_main_mma, cudaFuncAttributeMaxDynamicSharedMemorySize, SMEM_MAIN);

    k_transpose<<<dim3(NHW/32, NC/32, NB), dim3(32,8)>>>(x);
    k_prep_wAf<<<(36*4096+255)/256, 256>>>(weight);
    k_prep_w27h<<<(72*8*32+255)/256, 256>>>(offset_w, mod_w);
    k_conv27<<<dim3(NHW/128, NB), 256>>>(offset_b, mod_b);
    k_main_mma<<<dim3(NHW/128, NB), 256, SMEM_MAIN>>>(bias, out);
}

// round 12
// speedup vs baseline: 1.0428x; 1.0428x over previous
#include <cuda_runtime.h>
#include <cuda_fp16.h>
#include <math.h>
#include <stddef.h>
#include <stdint.h>

#define NB 4
#define NC 128
#define NCO 256
#define NH 96
#define NW 96
#define NHW (NH*NW)          // 9216
#define NKK 9
#define NKDIM (NKK*NC)       // 1152

// ---- scratch (static device allocations) ----
__device__ __half  g_xh[(size_t)NB*NHW*NC];     // x as NHWC fp16 (9.4 MB)
__device__ __half2 g_wAf[36*4096];              // main weights, FRAGMENT order
__device__ __half2 g_w27h[72*8*32];             // conv27 weights [k2 global][ch]
__device__ float   g_meta[(size_t)NB*NKK*NHW*8];// per (b,kk,px): 4 weights + 4 indices

static __device__ __forceinline__ unsigned su32(const void* p){
    return (unsigned)__cvta_generic_to_shared(p);
}
static __device__ __forceinline__ void mma_f16(float* c, const uint32_t* a, const uint32_t* b){
    asm volatile("mma.sync.aligned.m16n8k16.row.col.f32.f16.f16.f32 "
        "{%0,%1,%2,%3}, {%4,%5,%6,%7}, {%8,%9}, {%0,%1,%2,%3};"
        : "+f"(c[0]), "+f"(c[1]), "+f"(c[2]), "+f"(c[3])
        : "r"(a[0]), "r"(a[1]), "r"(a[2]), "r"(a[3]), "r"(b[0]), "r"(b[1]));
}
static __device__ __forceinline__ void cpa_wait0(){
    asm volatile("cp.async.wait_group 0;\n" ::: "memory");
}

// ---------------- transpose x: NCHW fp32 -> NHWC fp16 ----------------
__global__ void k_transpose(const float* __restrict__ x){
    __shared__ float tile[32][33];
    int b = blockIdx.z, c0 = blockIdx.y*32, p0 = blockIdx.x*32;
    int tx = threadIdx.x, ty = threadIdx.y;
    int t = ty*32 + tx;
#pragma unroll
    for (int i = ty; i < 32; i += 8)
        tile[i][tx] = x[((size_t)(b*NC + c0 + i))*NHW + p0 + tx];
    __syncthreads();
#pragma unroll
    for (int it = 0; it < 2; it++){
        int idx = it*256 + t;
        int p = idx >> 4, q = idx & 15;
        __half2 h = __floats2half2_rn(tile[2*q][p], tile[2*q+1][p]);
        *(__half2*)&g_xh[(size_t)(b*NHW + p0 + p)*NC + c0 + 2*q] = h;
    }
}

// ---------------- weight prep: fragment-order for main GEMM ----------------
__global__ void k_prep_wAf(const float* __restrict__ w){
    int idx = blockIdx.x*256 + threadIdx.x;
    if (idx >= 36*4096) return;
    int chunk = idx >> 12;
    int rem   = idx & 4095;
    int ks    = rem >> 11;
    int mtg   = (rem >> 7) & 15;
    int lane  = (rem >> 2) & 31;
    int r     = rem & 3;
    int acol = lane & 3, arow = lane >> 2;
    int k2 = chunk*16 + ks*8 + acol + ((r>>1)<<2);
    int co = mtg*16 + arow + ((r&1)<<3);
    int k = 2*k2;
    int kk = k >> 7, c = k & 127;
    float w0 = w[(size_t)(co*NC + c)*NKK + kk];
    float w1 = w[(size_t)(co*NC + c + 1)*NKK + kk];
    g_wAf[idx] = __floats2half2_rn(w0, w1);
}

__global__ void k_prep_w27h(const float* __restrict__ ow, const float* __restrict__ mw){
    int idx = blockIdx.x*256 + threadIdx.x;
    if (idx >= 72*8*32) return;
    int ch = idx & 31, r = idx >> 5;
    int stage = r >> 3, k2 = r & 7;
    int k = stage*16 + 2*k2;
    int kk = k >> 7, c = k & 127;
    float v0 = 0.f, v1 = 0.f;
    if (ch < 18){      v0 = ow[(size_t)(ch*NC + c)*NKK + kk];
                       v1 = ow[(size_t)(ch*NC + c + 1)*NKK + kk]; }
    else if (ch < 27){ v0 = mw[(size_t)((ch-18)*NC + c)*NKK + kk];
                       v1 = mw[(size_t)((ch-18)*NC + c + 1)*NKK + kk]; }
    g_w27h[idx] = __floats2half2_rn(v0, v1);
}

// ---------------- conv27 (offsets + modulation) fp16 mma + meta build ------
// Block: 128 px x 32 ch. 256 threads, 8 warps x (32ch x 16px). 36 K32 stages.
#define C_AS 40
#define C_BS 136
#define OPAD 130
__global__ __launch_bounds__(256,2) void k_conv27(const float* __restrict__ off_b,
                                                  const float* __restrict__ mod_b){
    __shared__ __half2 A2c[2][16*C_AS];
    __shared__ __half2 B2c[2][16*C_BS];
    __shared__ float sOut[32][OPAD];

    const int b = blockIdx.y, p0 = blockIdx.x*128;
    const int t = threadIdx.x;
    const int wid = t>>5, lane = t&31;
    const int bpx = t>>2, bcq = t&3;
    const int arow = lane>>2, acol = lane&3;
    const int wn = wid*16;
    const __half* __restrict__ xb = g_xh + (size_t)b*NHW*NC;

    const __half* gp0 = xb; const __half* gp1 = xb;
    bool v0=false, v1=false;
    uint4 r0, r1;

    float acc[2][2][4];
#pragma unroll
    for (int i=0;i<2;i++)
#pragma unroll
        for (int j=0;j<2;j++)
#pragma unroll
            for (int q=0;q<4;q++) acc[i][j][q]=0.f;

    auto geom = [&](int kk){
        int ky = kk/3, kx = kk - ky*3;
#pragma unroll
        for (int i=0;i<2;i++){
            int p = p0 + bpx + 64*i;
            int h = p/96, w = p - h*96;
            int sy = h - 1 + ky, sx = w - 1 + kx;
            bool v = ((unsigned)sy < 96u) && ((unsigned)sx < 96u);
            const __half* gp = xb + (ptrdiff_t)(sy*96 + sx)*NC;
            if (i==0){ v0=v; gp0=gp; } else { v1=v; gp1=gp; }
        }
    };
    auto issue_a = [&](int s, int buf){
        if (t < 128){
            int row = t>>3, seg = t&7;
            unsigned d = su32(&A2c[buf][row*C_AS + seg*4]);
            const __half2* src = g_w27h + (size_t)(s*16 + row)*32 + seg*4;
            asm volatile("cp.async.cg.shared.global [%0], [%1], 16;\n" :: "r"(d), "l"(src));
        }
        asm volatile("cp.async.commit_group;\n");
    };
    auto issue_b = [&](int s){
        int c = (s&3)*32 + (bcq<<3);
        r0 = make_uint4(0u,0u,0u,0u);
        r1 = make_uint4(0u,0u,0u,0u);
        if (v0) r0 = *(const uint4*)(gp0 + c);
        if (v1) r1 = *(const uint4*)(gp1 + c);
    };
    auto store_b = [&](int buf){
        int xr = bcq<<3;
        const uint32_t* w0 = &r0.x;
        const uint32_t* w1 = &r1.x;
#pragma unroll
        for (int j=0;j<4;j++){
            int k2 = 4*bcq + j;
            *(uint32_t*)&B2c[buf][k2*C_BS + (bpx ^ xr)] = w0[j];
            *(uint32_t*)&B2c[buf][k2*C_BS + ((bpx+64) ^ xr)] = w1[j];
        }
    };

    geom(0);
    issue_a(0,0); issue_b(0); store_b(0);
    cpa_wait0();
    __syncthreads();

    for (int s=0;s<36;s++){
        int cur = s&1;
        if (s<35){
            issue_a(s+1, cur^1);
            if (((s+1)&3)==0) geom((s+1)>>2);
            issue_b(s+1);
        }
        const __half2* Ab = A2c[cur];
        const __half2* Bb = B2c[cur];
#pragma unroll
        for (int ks=0; ks<2; ks++){
            uint32_t a[2][4];
#pragma unroll
            for (int mt=0;mt<2;mt++){
                a[mt][0] = *(const uint32_t*)&Ab[(ks*8+acol)*C_AS + 16*mt + arow];
                a[mt][1] = *(const uint32_t*)&Ab[(ks*8+acol)*C_AS + 16*mt + arow + 8];
                a[mt][2] = *(const uint32_t*)&Ab[(ks*8+acol+4)*C_AS + 16*mt + arow];
                a[mt][3] = *(const uint32_t*)&Ab[(ks*8+acol+4)*C_AS + 16*mt + arow + 8];
            }
            int xr0 = ((ks*8+acol)>>2)<<3;
            int xr1 = ((ks*8+acol+4)>>2)<<3;
            uint32_t bq[2][2];
#pragma unroll
            for (int nt=0;nt<2;nt++){
                int pxn = wn + 8*nt + arow;
                bq[nt][0] = *(const uint32_t*)&Bb[(ks*8+acol)*C_BS + (pxn ^ xr0)];
                bq[nt][1] = *(const uint32_t*)&Bb[(ks*8+acol+4)*C_BS + (pxn ^ xr1)];
            }
#pragma unroll
            for (int mt=0;mt<2;mt++)
#pragma unroll
                for (int nt=0;nt<2;nt++)
                    mma_f16(acc[mt][nt], a[mt], bq[nt]);
        }

        if (s<35){
            store_b(cur^1);
            cpa_wait0();
        }
        __syncthreads();
    }

    // write conv output fragments to sOut
#pragma unroll
    for (int mt=0;mt<2;mt++)
#pragma unroll
        for (int nt=0;nt<2;nt++){
            int row = 16*mt + arow;
            int col = wn + 8*nt + 2*acol;
            float* cp = &sOut[row][col];
            cp[0] = acc[mt][nt][0]; cp[1] = acc[mt][nt][1];
            cp[8*OPAD] = acc[mt][nt][2]; cp[8*OPAD+1] = acc[mt][nt][3];
        }
    __syncthreads();

    if (t < 128){
        int p = p0 + t;
        int h = p/96, w = p - h*96;
#pragma unroll
        for (int kk=0; kk<9; kk++){
            float dy = sOut[2*kk  ][t] + off_b[2*kk];
            float dx = sOut[2*kk+1][t] + off_b[2*kk+1];
            float mp = sOut[18+kk][t] + mod_b[kk];
            float m  = 1.f/(1.f + expf(-mp));
            int ky = kk/3, kx = kk - ky*3;
            float py  = (float)(h - 1 + ky) + dy;
            float pxf = (float)(w - 1 + kx) + dx;
            float fy = floorf(py), fx = floorf(pxf);
            float ly = py - fy,  lx = pxf - fx;
            int y0 = (int)fy, x0 = (int)fx;
            int y1 = y0+1,   x1 = x0+1;
            bool vy0 = (unsigned)y0 < 96u, vy1 = (unsigned)y1 < 96u;
            bool vx0 = (unsigned)x0 < 96u, vx1 = (unsigned)x1 < 96u;
            float hy = 1.f - ly, hx = 1.f - lx;
            float w00 = (vy0&&vx0) ? hy*hx*m : 0.f;
            float w01 = (vy0&&vx1) ? hy*lx*m : 0.f;
            float w10 = (vy1&&vx0) ? ly*hx*m : 0.f;
            float w11 = (vy1&&vx1) ? ly*lx*m : 0.f;
            int cy0 = min(max(y0,0),95), cy1 = min(max(y1,0),95);
            int cx0 = min(max(x0,0),95), cx1 = min(max(x1,0),95);
            int i00 = (cy0*96+cx0)*NC, i01 = (cy0*96+cx1)*NC;
            int i10 = (cy1*96+cx0)*NC, i11 = (cy1*96+cx1)*NC;
            float* mo = &g_meta[((size_t)(b*NKK+kk)*NHW + p)*8];
            *(float4*)mo = make_float4(w00,w01,w10,w11);
            *(float4*)(mo+4) = make_float4(__int_as_float(i00), __int_as_float(i01),
                                           __int_as_float(i10), __int_as_float(i11));
        }
    }
}

// ---------------- main fused deformable GEMM: mma.sync fp16 ----------------
// Block tile: 256co x 128px, K=1152 in 36 chunks of 32 (16 k2 rows).
// 256 threads, 8 warps (4m x 2n), warp tile 64co x 64px.
// A: fragment-order smem (LDS.128), 2-stage cp.async pipeline.
// B: swizzled [k2][px] smem, 2-stage; gather LOADS issued before the MMA
//    section, bilinear combine + store AFTER it (hides gather latency).
#define CHUNKS 36
#define A2H2 4096                 // half2 per A buffer
#define B2S 136
#define B2BUF (16*B2S)            // 2176 half2
#define SMEM_PIPE_BYTES ((2*A2H2 + 2*B2BUF)*4)   // 50176
#define SMEM_EPI_BYTES (128*132*4)               // 67584

__global__ __launch_bounds__(256,1) void k_main_mma(const float* __restrict__ bias,
                                                    float* __restrict__ out){
    extern __shared__ char smraw[];
    __half2* A2 = (__half2*)smraw;              // [2][4096] fragment order
    __half2* B2 = A2 + 2*A2H2;                  // [2][16][B2S]
    float*   Cs = (float*)smraw;                // epilogue [128][132]

    const int t = threadIdx.x;
    const int wid = t>>5, lane = t&31;
    const int b = blockIdx.y, p0 = blockIdx.x*128;
    const __half* __restrict__ xb = g_xh + (size_t)b*NHW*NC;

    const int pxb = t>>2, q = t&3;
    const int wm4 = (wid&3)*4, wn = (wid>>2)*64;
    const int arow = lane>>2, acol = lane&3;

    float4 mw0 = make_float4(0,0,0,0), mw1 = make_float4(0,0,0,0);
    int4 mi0 = make_int4(0,0,0,0), mi1 = make_int4(0,0,0,0);
    uint4 gu[8];                 // raw gathered data, held across MMA section
    __half2 rg[2][4];

    float acc[4][8][4];
#pragma unroll
    for (int i=0;i<4;i++)
#pragma unroll
        for (int j=0;j<8;j++)
#pragma unroll
            for (int qq=0;qq<4;qq++) acc[i][j][qq]=0.f;

    auto load_meta = [&](int kk){
        const float4* mp0 = (const float4*)&g_meta[((size_t)(b*NKK+kk)*NHW + p0 + pxb)*8];
        mw0 = mp0[0];
        float4 ti = mp0[1];
        mi0.x = __float_as_int(ti.x); mi0.y = __float_as_int(ti.y);
        mi0.z = __float_as_int(ti.z); mi0.w = __float_as_int(ti.w);
        const float4* mp1 = (const float4*)&g_meta[((size_t)(b*NKK+kk)*NHW + p0 + pxb + 64)*8];
        mw1 = mp1[0];
        float4 tj = mp1[1];
        mi1.x = __float_as_int(tj.x); mi1.y = __float_as_int(tj.y);
        mi1.z = __float_as_int(tj.z); mi1.w = __float_as_int(tj.w);
    };
    auto issue_a = [&](int chunk, int buf){
#pragma unroll
        for (int i=0;i<4;i++){
            int qq = t + 256*i;               // 0..1023, 16B each -> 16KB linear
            const __half2* src = g_wAf + (size_t)chunk*4096 + qq*4;
            unsigned dst = su32(A2 + buf*A2H2 + qq*4);
            asm volatile("cp.async.cg.shared.global [%0], [%1], 16;\n" :: "r"(dst), "l"(src));
        }
        asm volatile("cp.async.commit_group;\n");
    };
    // phase 1: issue the 8 gather loads into registers (no consumption)
    auto gather_load = [&](int chunk){
        int csub = (chunk&3)*32 + q*8;
        gu[0] = *(const uint4*)(xb + mi0.x + csub);
        gu[1] = *(const uint4*)(xb + mi0.y + csub);
        gu[2] = *(const uint4*)(xb + mi0.z + csub);
        gu[3] = *(const uint4*)(xb + mi0.w + csub);
        gu[4] = *(const uint4*)(xb + mi1.x + csub);
        gu[5] = *(const uint4*)(xb + mi1.y + csub);
        gu[6] = *(const uint4*)(xb + mi1.z + csub);
        gu[7] = *(const uint4*)(xb + mi1.w + csub);
    };
    // phase 2: bilinear combine (fp32) + fp16 round — runs after the MMA section
    auto gather_combine = [&](){
#pragma unroll
        for (int e=0;e<2;e++){
            const float4 mwv = e ? mw1 : mw0;
            const uint32_t* p0v = &gu[4*e+0].x;
            const uint32_t* p1v = &gu[4*e+1].x;
            const uint32_t* p2v = &gu[4*e+2].x;
            const uint32_t* p3v = &gu[4*e+3].x;
#pragma unroll
            for (int j=0;j<4;j++){
                float2 f0 = __half22float2(*(const __half2*)&p0v[j]);
                float2 f1 = __half22float2(*(const __half2*)&p1v[j]);
                float2 f2 = __half22float2(*(const __half2*)&p2v[j]);
                float2 f3 = __half22float2(*(const __half2*)&p3v[j]);
                float vx = mwv.x*f0.x + mwv.y*f1.x + mwv.z*f2.x + mwv.w*f3.x;
                float vy = mwv.x*f0.y + mwv.y*f1.y + mwv.z*f2.y + mwv.w*f3.y;
                rg[e][j] = __floats2half2_rn(vx, vy);
            }
        }
    };
    auto store_b = [&](int buf){
        int xr = ((q>>1)<<4) ^ ((q&1)<<3);
#pragma unroll
        for (int j=0;j<4;j++){
            int k2 = q*4 + j;
            B2[buf*B2BUF + k2*B2S + (pxb ^ xr)] = rg[0][j];
            B2[buf*B2BUF + k2*B2S + ((pxb+64) ^ xr)] = rg[1][j];
        }
    };

    // prologue
    load_meta(0);
    gather_load(0);
    issue_a(0, 0);
    gather_combine();
    store_b(0);
    cpa_wait0();
    __syncthreads();

    for (int chunk=0; chunk<CHUNKS; chunk++){
        const int cur = chunk&1;
        if (chunk < CHUNKS-1){
            if (((chunk+1)&3)==0) load_meta((chunk+1)>>2);
            gather_load(chunk+1);          // LDGs in flight across the MMA section
            issue_a(chunk+1, cur^1);
        }

        const __half2* Ab = A2 + cur*A2H2;
        const __half2* Bb = B2 + cur*B2BUF;
#pragma unroll
        for (int ks=0; ks<2; ks++){
            uint32_t a[4][4];
#pragma unroll
            for (int mt=0;mt<4;mt++){
                uint4 av = *(const uint4*)(Ab + (ks*16 + wm4 + mt)*128 + lane*4);
                a[mt][0] = av.x; a[mt][1] = av.y; a[mt][2] = av.z; a[mt][3] = av.w;
            }
            uint32_t bq[8][2];
#pragma unroll
            for (int nt=0;nt<8;nt++){
                int pxn = (wn + 8*nt + arow) ^ (ks<<4);
                bq[nt][0] = *(const uint32_t*)&Bb[(ks*8+acol)*B2S + pxn];
                bq[nt][1] = *(const uint32_t*)&Bb[(ks*8+acol+4)*B2S + (pxn^8)];
            }
#pragma unroll
            for (int mt=0;mt<4;mt++)
#pragma unroll
                for (int nt=0;nt<8;nt++)
                    mma_f16(acc[mt][nt], a[mt], bq[nt]);
        }

        if (chunk < CHUNKS-1){
            gather_combine();              // loads have had the whole MMA section to land
            store_b(cur^1);
            cpa_wait0();
        }
        __syncthreads();
    }

    // ---- epilogue: stage C through smem in 2 co-halves, coalesced + bias ----
#pragma unroll
    for (int h=0; h<2; h++){
        __syncthreads();
        if (((wid&3)>>1) == h){
            int rbase = (wid&3)*64 - 128*h;   // 0 or 64
#pragma unroll
            for (int mt=0;mt<4;mt++){
#pragma unroll
                for (int nt=0;nt<8;nt++){
                    int row = rbase + 16*mt + arow;
                    int col = wn + nt*8 + 2*acol;
                    float* cp2 = Cs + row*132 + col;
                    cp2[0] = acc[mt][nt][0]; cp2[1] = acc[mt][nt][1];
                    cp2[8*132] = acc[mt][nt][2]; cp2[8*132+1] = acc[mt][nt][3];
                }
            }
        }
        __syncthreads();
        {
            int r = t>>1, seg = (t&1)*64;
            int co = 128*h + r;
            float bz = __ldg(&bias[co]);
            float* op = out + (size_t)(b*NCO + co)*NHW + p0 + seg;
            const float* cr = Cs + r*132 + seg;
#pragma unroll
            for (int j=0;j<16;j++){
                float4 v = *(const float4*)(cr + j*4);
                v.x += bz; v.y += bz; v.z += bz; v.w += bz;
                *(float4*)(op + j*4) = v;
            }
        }
    }
}

// ---------------- launch ----------------
extern "C" void kernel_launch(void* const* d_in, const int* in_sizes, int n_in,
                              void* d_out, int out_size){
    (void)in_sizes; (void)n_in; (void)out_size;
    const float* x        = (const float*)d_in[0];
    const float* weight   = (const float*)d_in[1];
    const float* bias     = (const float*)d_in[2];
    const float* offset_w = (const float*)d_in[3];
    const float* offset_b = (const float*)d_in[4];
    const float* mod_w    = (const float*)d_in[5];
    const float* mod_b    = (const float*)d_in[6];
    float* out = (float*)d_out;

    const int SMEM_MAIN = (SMEM_PIPE_BYTES > SMEM_EPI_BYTES) ? SMEM_PIPE_BYTES : SMEM_EPI_BYTES;
    cudaFuncSetAttribute(k_main_mma, cudaFuncAttributeMaxDynamicSharedMemorySize, SMEM_MAIN);

    k_transpose<<<dim3(NHW/32, NC/32, NB), dim3(32,8)>>>(x);
    k_prep_wAf<<<(36*4096+255)/256, 256>>>(weight);
    k_prep_w27h<<<(72*8*32+255)/256, 256>>>(offset_w, mod_w);
    k_conv27<<<dim3(NHW/128, NB), 256>>>(offset_b, mod_b);
    k_main_mma<<<dim3(NHW/128, NB), 256, SMEM_MAIN>>>(bias, out);
}

// round 13
// speedup vs baseline: 1.1245x; 1.0783x over previous
#include <cuda_runtime.h>
#include <cuda_fp16.h>
#include <math.h>
#include <stddef.h>
#include <stdint.h>

#define NB 4
#define NC 128
#define NCO 256
#define NH 96
#define NW 96
#define NHW (NH*NW)          // 9216
#define NKK 9
#define NKDIM (NKK*NC)       // 1152

// ---- scratch (static device allocations) ----
__device__ __half  g_xh[(size_t)NB*NHW*NC];     // x as NHWC fp16 (9.4 MB)
__device__ __half2 g_wAf[36*4096];              // main weights, FRAGMENT order
__device__ __half2 g_w27h[72*8*32];             // conv27 weights [k2 global][ch]
__device__ float   g_meta[(size_t)NB*NKK*NHW*8];// per (b,kk,px): 4 weights + 4 indices

static __device__ __forceinline__ unsigned su32(const void* p){
    return (unsigned)__cvta_generic_to_shared(p);
}
static __device__ __forceinline__ void mma_f16(float* c, const uint32_t* a, const uint32_t* b){
    asm volatile("mma.sync.aligned.m16n8k16.row.col.f32.f16.f16.f32 "
        "{%0,%1,%2,%3}, {%4,%5,%6,%7}, {%8,%9}, {%0,%1,%2,%3};"
        : "+f"(c[0]), "+f"(c[1]), "+f"(c[2]), "+f"(c[3])
        : "r"(a[0]), "r"(a[1]), "r"(a[2]), "r"(a[3]), "r"(b[0]), "r"(b[1]));
}
static __device__ __forceinline__ void cpa_wait0(){
    asm volatile("cp.async.wait_group 0;\n" ::: "memory");
}

// ---------------- transpose x: NCHW fp32 -> NHWC fp16 ----------------
__global__ void k_transpose(const float* __restrict__ x){
    __shared__ float tile[32][33];
    int b = blockIdx.z, c0 = blockIdx.y*32, p0 = blockIdx.x*32;
    int tx = threadIdx.x, ty = threadIdx.y;
    int t = ty*32 + tx;
#pragma unroll
    for (int i = ty; i < 32; i += 8)
        tile[i][tx] = x[((size_t)(b*NC + c0 + i))*NHW + p0 + tx];
    __syncthreads();
#pragma unroll
    for (int it = 0; it < 2; it++){
        int idx = it*256 + t;
        int p = idx >> 4, q = idx & 15;
        __half2 h = __floats2half2_rn(tile[2*q][p], tile[2*q+1][p]);
        *(__half2*)&g_xh[(size_t)(b*NHW + p0 + p)*NC + c0 + 2*q] = h;
    }
}

// ---------------- weight prep: fragment-order for main GEMM ----------------
__global__ void k_prep_wAf(const float* __restrict__ w){
    int idx = blockIdx.x*256 + threadIdx.x;
    if (idx >= 36*4096) return;
    int chunk = idx >> 12;
    int rem   = idx & 4095;
    int ks    = rem >> 11;
    int mtg   = (rem >> 7) & 15;
    int lane  = (rem >> 2) & 31;
    int r     = rem & 3;
    int acol = lane & 3, arow = lane >> 2;
    int k2 = chunk*16 + ks*8 + acol + ((r>>1)<<2);
    int co = mtg*16 + arow + ((r&1)<<3);
    int k = 2*k2;
    int kk = k >> 7, c = k & 127;
    float w0 = w[(size_t)(co*NC + c)*NKK + kk];
    float w1 = w[(size_t)(co*NC + c + 1)*NKK + kk];
    g_wAf[idx] = __floats2half2_rn(w0, w1);
}

__global__ void k_prep_w27h(const float* __restrict__ ow, const float* __restrict__ mw){
    int idx = blockIdx.x*256 + threadIdx.x;
    if (idx >= 72*8*32) return;
    int ch = idx & 31, r = idx >> 5;
    int stage = r >> 3, k2 = r & 7;
    int k = stage*16 + 2*k2;
    int kk = k >> 7, c = k & 127;
    float v0 = 0.f, v1 = 0.f;
    if (ch < 18){      v0 = ow[(size_t)(ch*NC + c)*NKK + kk];
                       v1 = ow[(size_t)(ch*NC + c + 1)*NKK + kk]; }
    else if (ch < 27){ v0 = mw[(size_t)((ch-18)*NC + c)*NKK + kk];
                       v1 = mw[(size_t)((ch-18)*NC + c + 1)*NKK + kk]; }
    g_w27h[idx] = __floats2half2_rn(v0, v1);
}

// ---------------- conv27 (offsets + modulation) fp16 mma + meta build ------
// Block: 128 px x 32 ch. 256 threads, 8 warps x (32ch x 16px). 36 K32 stages.
#define C_AS 40
#define C_BS 136
#define OPAD 130
__global__ __launch_bounds__(256,2) void k_conv27(const float* __restrict__ off_b,
                                                  const float* __restrict__ mod_b){
    __shared__ __half2 A2c[2][16*C_AS];
    __shared__ __half2 B2c[2][16*C_BS];
    __shared__ float sOut[32][OPAD];

    const int b = blockIdx.y, p0 = blockIdx.x*128;
    const int t = threadIdx.x;
    const int wid = t>>5, lane = t&31;
    const int bpx = t>>2, bcq = t&3;
    const int arow = lane>>2, acol = lane&3;
    const int wn = wid*16;
    const __half* __restrict__ xb = g_xh + (size_t)b*NHW*NC;

    const __half* gp0 = xb; const __half* gp1 = xb;
    bool v0=false, v1=false;
    uint4 r0, r1;

    float acc[2][2][4];
#pragma unroll
    for (int i=0;i<2;i++)
#pragma unroll
        for (int j=0;j<2;j++)
#pragma unroll
            for (int q=0;q<4;q++) acc[i][j][q]=0.f;

    auto geom = [&](int kk){
        int ky = kk/3, kx = kk - ky*3;
#pragma unroll
        for (int i=0;i<2;i++){
            int p = p0 + bpx + 64*i;
            int h = p/96, w = p - h*96;
            int sy = h - 1 + ky, sx = w - 1 + kx;
            bool v = ((unsigned)sy < 96u) && ((unsigned)sx < 96u);
            const __half* gp = xb + (ptrdiff_t)(sy*96 + sx)*NC;
            if (i==0){ v0=v; gp0=gp; } else { v1=v; gp1=gp; }
        }
    };
    auto issue_a = [&](int s, int buf){
        if (t < 128){
            int row = t>>3, seg = t&7;
            unsigned d = su32(&A2c[buf][row*C_AS + seg*4]);
            const __half2* src = g_w27h + (size_t)(s*16 + row)*32 + seg*4;
            asm volatile("cp.async.cg.shared.global [%0], [%1], 16;\n" :: "r"(d), "l"(src));
        }
        asm volatile("cp.async.commit_group;\n");
    };
    auto issue_b = [&](int s){
        int c = (s&3)*32 + (bcq<<3);
        r0 = make_uint4(0u,0u,0u,0u);
        r1 = make_uint4(0u,0u,0u,0u);
        if (v0) r0 = *(const uint4*)(gp0 + c);
        if (v1) r1 = *(const uint4*)(gp1 + c);
    };
    auto store_b = [&](int buf){
        int xr = bcq<<3;
        const uint32_t* w0 = &r0.x;
        const uint32_t* w1 = &r1.x;
#pragma unroll
        for (int j=0;j<4;j++){
            int k2 = 4*bcq + j;
            *(uint32_t*)&B2c[buf][k2*C_BS + (bpx ^ xr)] = w0[j];
            *(uint32_t*)&B2c[buf][k2*C_BS + ((bpx+64) ^ xr)] = w1[j];
        }
    };

    geom(0);
    issue_a(0,0); issue_b(0); store_b(0);
    cpa_wait0();
    __syncthreads();

    for (int s=0;s<36;s++){
        int cur = s&1;
        if (s<35){
            issue_a(s+1, cur^1);
            if (((s+1)&3)==0) geom((s+1)>>2);
            issue_b(s+1);
        }
        const __half2* Ab = A2c[cur];
        const __half2* Bb = B2c[cur];
#pragma unroll
        for (int ks=0; ks<2; ks++){
            uint32_t a[2][4];
#pragma unroll
            for (int mt=0;mt<2;mt++){
                a[mt][0] = *(const uint32_t*)&Ab[(ks*8+acol)*C_AS + 16*mt + arow];
                a[mt][1] = *(const uint32_t*)&Ab[(ks*8+acol)*C_AS + 16*mt + arow + 8];
                a[mt][2] = *(const uint32_t*)&Ab[(ks*8+acol+4)*C_AS + 16*mt + arow];
                a[mt][3] = *(const uint32_t*)&Ab[(ks*8+acol+4)*C_AS + 16*mt + arow + 8];
            }
            int xr0 = ((ks*8+acol)>>2)<<3;
            int xr1 = ((ks*8+acol+4)>>2)<<3;
            uint32_t bq[2][2];
#pragma unroll
            for (int nt=0;nt<2;nt++){
                int pxn = wn + 8*nt + arow;
                bq[nt][0] = *(const uint32_t*)&Bb[(ks*8+acol)*C_BS + (pxn ^ xr0)];
                bq[nt][1] = *(const uint32_t*)&Bb[(ks*8+acol+4)*C_BS + (pxn ^ xr1)];
            }
#pragma unroll
            for (int mt=0;mt<2;mt++)
#pragma unroll
                for (int nt=0;nt<2;nt++)
                    mma_f16(acc[mt][nt], a[mt], bq[nt]);
        }

        if (s<35){
            store_b(cur^1);
            cpa_wait0();
        }
        __syncthreads();
    }

    // write conv output fragments to sOut
#pragma unroll
    for (int mt=0;mt<2;mt++)
#pragma unroll
        for (int nt=0;nt<2;nt++){
            int row = 16*mt + arow;
            int col = wn + 8*nt + 2*acol;
            float* cp = &sOut[row][col];
            cp[0] = acc[mt][nt][0]; cp[1] = acc[mt][nt][1];
            cp[8*OPAD] = acc[mt][nt][2]; cp[8*OPAD+1] = acc[mt][nt][3];
        }
    __syncthreads();

    if (t < 128){
        int p = p0 + t;
        int h = p/96, w = p - h*96;
#pragma unroll
        for (int kk=0; kk<9; kk++){
            float dy = sOut[2*kk  ][t] + off_b[2*kk];
            float dx = sOut[2*kk+1][t] + off_b[2*kk+1];
            float mp = sOut[18+kk][t] + mod_b[kk];
            float m  = 1.f/(1.f + expf(-mp));
            int ky = kk/3, kx = kk - ky*3;
            float py  = (float)(h - 1 + ky) + dy;
            float pxf = (float)(w - 1 + kx) + dx;
            float fy = floorf(py), fx = floorf(pxf);
            float ly = py - fy,  lx = pxf - fx;
            int y0 = (int)fy, x0 = (int)fx;
            int y1 = y0+1,   x1 = x0+1;
            bool vy0 = (unsigned)y0 < 96u, vy1 = (unsigned)y1 < 96u;
            bool vx0 = (unsigned)x0 < 96u, vx1 = (unsigned)x1 < 96u;
            float hy = 1.f - ly, hx = 1.f - lx;
            float w00 = (vy0&&vx0) ? hy*hx*m : 0.f;
            float w01 = (vy0&&vx1) ? hy*lx*m : 0.f;
            float w10 = (vy1&&vx0) ? ly*hx*m : 0.f;
            float w11 = (vy1&&vx1) ? ly*lx*m : 0.f;
            int cy0 = min(max(y0,0),95), cy1 = min(max(y1,0),95);
            int cx0 = min(max(x0,0),95), cx1 = min(max(x1,0),95);
            int i00 = (cy0*96+cx0)*NC, i01 = (cy0*96+cx1)*NC;
            int i10 = (cy1*96+cx0)*NC, i11 = (cy1*96+cx1)*NC;
            float* mo = &g_meta[((size_t)(b*NKK+kk)*NHW + p)*8];
            *(float4*)mo = make_float4(w00,w01,w10,w11);
            *(float4*)(mo+4) = make_float4(__int_as_float(i00), __int_as_float(i01),
                                           __int_as_float(i10), __int_as_float(i11));
        }
    }
}

// ---------------- main fused deformable GEMM: mma.sync fp16 ----------------
// Block tile: 256co x 128px, K=1152 in 36 chunks of 32 (16 k2 rows).
// 256 threads, 8 warps (4m x 2n), warp tile 64co x 64px.
// A: fragment-order smem (LDS.128), 2-stage cp.async pipeline.
// B: swizzled [k2][px] smem, 2-stage; bilinear combine in packed fp16
//    (HMUL2/HFMA2 — no H2F cvts) to cut issue count.
#define CHUNKS 36
#define A2H2 4096                 // half2 per A buffer
#define B2S 136
#define B2BUF (16*B2S)            // 2176 half2
#define SMEM_PIPE_BYTES ((2*A2H2 + 2*B2BUF)*4)   // 50176
#define SMEM_EPI_BYTES (128*132*4)               // 67584

__global__ __launch_bounds__(256,1) void k_main_mma(const float* __restrict__ bias,
                                                    float* __restrict__ out){
    extern __shared__ char smraw[];
    __half2* A2 = (__half2*)smraw;              // [2][4096] fragment order
    __half2* B2 = A2 + 2*A2H2;                  // [2][16][B2S]
    float*   Cs = (float*)smraw;                // epilogue [128][132]

    const int t = threadIdx.x;
    const int wid = t>>5, lane = t&31;
    const int b = blockIdx.y, p0 = blockIdx.x*128;
    const __half* __restrict__ xb = g_xh + (size_t)b*NHW*NC;

    const int pxb = t>>2, q = t&3;
    const int wm4 = (wid&3)*4, wn = (wid>>2)*64;
    const int arow = lane>>2, acol = lane&3;

    __half2 hw0[4], hw1[4];      // bilinear weights broadcast to half2
    int4 mi0 = make_int4(0,0,0,0), mi1 = make_int4(0,0,0,0);
    uint4 gu[8];                 // raw gathered data
    __half2 rg[2][4];

    float acc[4][8][4];
#pragma unroll
    for (int i=0;i<4;i++)
#pragma unroll
        for (int j=0;j<8;j++)
#pragma unroll
            for (int qq=0;qq<4;qq++) acc[i][j][qq]=0.f;

    auto load_meta = [&](int kk){
        const float4* mp0 = (const float4*)&g_meta[((size_t)(b*NKK+kk)*NHW + p0 + pxb)*8];
        float4 mw0 = mp0[0];
        float4 ti = mp0[1];
        mi0.x = __float_as_int(ti.x); mi0.y = __float_as_int(ti.y);
        mi0.z = __float_as_int(ti.z); mi0.w = __float_as_int(ti.w);
        const float4* mp1 = (const float4*)&g_meta[((size_t)(b*NKK+kk)*NHW + p0 + pxb + 64)*8];
        float4 mw1 = mp1[0];
        float4 tj = mp1[1];
        mi1.x = __float_as_int(tj.x); mi1.y = __float_as_int(tj.y);
        mi1.z = __float_as_int(tj.z); mi1.w = __float_as_int(tj.w);
        hw0[0] = __float2half2_rn(mw0.x); hw0[1] = __float2half2_rn(mw0.y);
        hw0[2] = __float2half2_rn(mw0.z); hw0[3] = __float2half2_rn(mw0.w);
        hw1[0] = __float2half2_rn(mw1.x); hw1[1] = __float2half2_rn(mw1.y);
        hw1[2] = __float2half2_rn(mw1.z); hw1[3] = __float2half2_rn(mw1.w);
    };
    auto issue_a = [&](int chunk, int buf){
#pragma unroll
        for (int i=0;i<4;i++){
            int qq = t + 256*i;               // 0..1023, 16B each -> 16KB linear
            const __half2* src = g_wAf + (size_t)chunk*4096 + qq*4;
            unsigned dst = su32(A2 + buf*A2H2 + qq*4);
            asm volatile("cp.async.cg.shared.global [%0], [%1], 16;\n" :: "r"(dst), "l"(src));
        }
        asm volatile("cp.async.commit_group;\n");
    };
    auto gather_load = [&](int chunk){
        int csub = (chunk&3)*32 + q*8;
        gu[0] = *(const uint4*)(xb + mi0.x + csub);
        gu[1] = *(const uint4*)(xb + mi0.y + csub);
        gu[2] = *(const uint4*)(xb + mi0.z + csub);
        gu[3] = *(const uint4*)(xb + mi0.w + csub);
        gu[4] = *(const uint4*)(xb + mi1.x + csub);
        gu[5] = *(const uint4*)(xb + mi1.y + csub);
        gu[6] = *(const uint4*)(xb + mi1.z + csub);
        gu[7] = *(const uint4*)(xb + mi1.w + csub);
    };
    // bilinear combine in packed fp16: 4 HMUL2/HFMA2 per half2 output
    auto gather_combine = [&](){
#pragma unroll
        for (int e=0;e<2;e++){
            const __half2* hw = e ? hw1 : hw0;
            const uint32_t* p0v = &gu[4*e+0].x;
            const uint32_t* p1v = &gu[4*e+1].x;
            const uint32_t* p2v = &gu[4*e+2].x;
            const uint32_t* p3v = &gu[4*e+3].x;
#pragma unroll
            for (int j=0;j<4;j++){
                __half2 v = __hmul2(hw[0], *(const __half2*)&p0v[j]);
                v = __hfma2(hw[1], *(const __half2*)&p1v[j], v);
                v = __hfma2(hw[2], *(const __half2*)&p2v[j], v);
                v = __hfma2(hw[3], *(const __half2*)&p3v[j], v);
                rg[e][j] = v;
            }
        }
    };
    auto store_b = [&](int buf){
        int xr = ((q>>1)<<4) ^ ((q&1)<<3);
#pragma unroll
        for (int j=0;j<4;j++){
            int k2 = q*4 + j;
            B2[buf*B2BUF + k2*B2S + (pxb ^ xr)] = rg[0][j];
            B2[buf*B2BUF + k2*B2S + ((pxb+64) ^ xr)] = rg[1][j];
        }
    };

    // prologue
    load_meta(0);
    gather_load(0);
    issue_a(0, 0);
    gather_combine();
    store_b(0);
    cpa_wait0();
    __syncthreads();

    for (int chunk=0; chunk<CHUNKS; chunk++){
        const int cur = chunk&1;
        if (chunk < CHUNKS-1){
            if (((chunk+1)&3)==0) load_meta((chunk+1)>>2);
            gather_load(chunk+1);
            issue_a(chunk+1, cur^1);
        }

        const __half2* Ab = A2 + cur*A2H2;
        const __half2* Bb = B2 + cur*B2BUF;
#pragma unroll
        for (int ks=0; ks<2; ks++){
            uint32_t a[4][4];
#pragma unroll
            for (int mt=0;mt<4;mt++){
                uint4 av = *(const uint4*)(Ab + (ks*16 + wm4 + mt)*128 + lane*4);
                a[mt][0] = av.x; a[mt][1] = av.y; a[mt][2] = av.z; a[mt][3] = av.w;
            }
            uint32_t bq[8][2];
#pragma unroll
            for (int nt=0;nt<8;nt++){
                int pxn = (wn + 8*nt + arow) ^ (ks<<4);
                bq[nt][0] = *(const uint32_t*)&Bb[(ks*8+acol)*B2S + pxn];
                bq[nt][1] = *(const uint32_t*)&Bb[(ks*8+acol+4)*B2S + (pxn^8)];
            }
#pragma unroll
            for (int mt=0;mt<4;mt++)
#pragma unroll
                for (int nt=0;nt<8;nt++)
                    mma_f16(acc[mt][nt], a[mt], bq[nt]);
        }

        if (chunk < CHUNKS-1){
            gather_combine();
            store_b(cur^1);
            cpa_wait0();
        }
        __syncthreads();
    }

    // ---- epilogue: stage C through smem in 2 co-halves, coalesced + bias ----
#pragma unroll
    for (int h=0; h<2; h++){
        __syncthreads();
        if (((wid&3)>>1) == h){
            int rbase = (wid&3)*64 - 128*h;   // 0 or 64
#pragma unroll
            for (int mt=0;mt<4;mt++){
#pragma unroll
                for (int nt=0;nt<8;nt++){
                    int row = rbase + 16*mt + arow;
                    int col = wn + nt*8 + 2*acol;
                    float* cp2 = Cs + row*132 + col;
                    cp2[0] = acc[mt][nt][0]; cp2[1] = acc[mt][nt][1];
                    cp2[8*132] = acc[mt][nt][2]; cp2[8*132+1] = acc[mt][nt][3];
                }
            }
        }
        __syncthreads();
        {
            int r = t>>1, seg = (t&1)*64;
            int co = 128*h + r;
            float bz = __ldg(&bias[co]);
            float* op = out + (size_t)(b*NCO + co)*NHW + p0 + seg;
            const float* cr = Cs + r*132 + seg;
#pragma unroll
            for (int j=0;j<16;j++){
                float4 v = *(const float4*)(cr + j*4);
                v.x += bz; v.y += bz; v.z += bz; v.w += bz;
                *(float4*)(op + j*4) = v;
            }
        }
    }
}

// ---------------- launch ----------------
extern "C" void kernel_launch(void* const* d_in, const int* in_sizes, int n_in,
                              void* d_out, int out_size){
    (void)in_sizes; (void)n_in; (void)out_size;
    const float* x        = (const float*)d_in[0];
    const float* weight   = (const float*)d_in[1];
    const float* bias     = (const float*)d_in[2];
    const float* offset_w = (const float*)d_in[3];
    const float* offset_b = (const float*)d_in[4];
    const float* mod_w    = (const float*)d_in[5];
    const float* mod_b    = (const float*)d_in[6];
    float* out = (float*)d_out;

    const int SMEM_MAIN = (SMEM_PIPE_BYTES > SMEM_EPI_BYTES) ? SMEM_PIPE_BYTES : SMEM_EPI_BYTES;
    cudaFuncSetAttribute(k_main_mma, cudaFuncAttributeMaxDynamicSharedMemorySize, SMEM_MAIN);

    k_transpose<<<dim3(NHW/32, NC/32, NB), dim3(32,8)>>>(x);
    k_prep_wAf<<<(36*4096+255)/256, 256>>>(weight);
    k_prep_w27h<<<(72*8*32+255)/256, 256>>>(offset_w, mod_w);
    k_conv27<<<dim3(NHW/128, NB), 256>>>(offset_b, mod_b);
    k_main_mma<<<dim3(NHW/128, NB), 256, SMEM_MAIN>>>(bias, out);
}

// round 14
// speedup vs baseline: 1.1393x; 1.0132x over previous
#include <cuda_runtime.h>
#include <cuda_fp16.h>
#include <math.h>
#include <stddef.h>
#include <stdint.h>

#define NB 4
#define NC 128
#define NCO 256
#define NH 96
#define NW 96
#define NHW (NH*NW)          // 9216
#define NKK 9
#define NKDIM (NKK*NC)       // 1152

// ---- scratch (static device allocations) ----
__device__ __half  g_xh[(size_t)NB*NHW*NC];     // x as NHWC fp16 (9.4 MB)
__device__ __half2 g_wAf[36*4096];              // main weights, FRAGMENT order
__device__ __half2 g_w27h[72*8*32];             // conv27 weights [k2 global][ch]
__device__ float   g_meta[(size_t)NB*NKK*NHW*8];// per (b,kk,px): 4 weights + 4 indices

static __device__ __forceinline__ unsigned su32(const void* p){
    return (unsigned)__cvta_generic_to_shared(p);
}
static __device__ __forceinline__ void mma_f16(float* c, const uint32_t* a, const uint32_t* b){
    asm volatile("mma.sync.aligned.m16n8k16.row.col.f32.f16.f16.f32 "
        "{%0,%1,%2,%3}, {%4,%5,%6,%7}, {%8,%9}, {%0,%1,%2,%3};"
        : "+f"(c[0]), "+f"(c[1]), "+f"(c[2]), "+f"(c[3])
        : "r"(a[0]), "r"(a[1]), "r"(a[2]), "r"(a[3]), "r"(b[0]), "r"(b[1]));
}
static __device__ __forceinline__ void cpa_wait0(){
    asm volatile("cp.async.wait_group 0;\n" ::: "memory");
}

// ---------------- transpose x: NCHW fp32 -> NHWC fp16 ----------------
__global__ void k_transpose(const float* __restrict__ x){
    __shared__ float tile[32][33];
    int b = blockIdx.z, c0 = blockIdx.y*32, p0 = blockIdx.x*32;
    int tx = threadIdx.x, ty = threadIdx.y;
    int t = ty*32 + tx;
#pragma unroll
    for (int i = ty; i < 32; i += 8)
        tile[i][tx] = x[((size_t)(b*NC + c0 + i))*NHW + p0 + tx];
    __syncthreads();
#pragma unroll
    for (int it = 0; it < 2; it++){
        int idx = it*256 + t;
        int p = idx >> 4, q = idx & 15;
        __half2 h = __floats2half2_rn(tile[2*q][p], tile[2*q+1][p]);
        *(__half2*)&g_xh[(size_t)(b*NHW + p0 + p)*NC + c0 + 2*q] = h;
    }
}

// ---------------- merged weight prep (main frag-order + conv27) -----------
// idx < 36*4096 : main GEMM weights in fragment order (same math as before)
// else          : conv27 weights [stage][k2][ch]
#define NWA (36*4096)
#define NW27 (72*8*32)
__global__ void k_prep_all(const float* __restrict__ w,
                           const float* __restrict__ ow,
                           const float* __restrict__ mw){
    int idx = blockIdx.x*256 + threadIdx.x;
    if (idx < NWA){
        int chunk = idx >> 12;
        int rem   = idx & 4095;
        int ks    = rem >> 11;
        int mtg   = (rem >> 7) & 15;
        int lane  = (rem >> 2) & 31;
        int r     = rem & 3;
        int acol = lane & 3, arow = lane >> 2;
        int k2 = chunk*16 + ks*8 + acol + ((r>>1)<<2);
        int co = mtg*16 + arow + ((r&1)<<3);
        int k = 2*k2;
        int kk = k >> 7, c = k & 127;
        float w0 = w[(size_t)(co*NC + c)*NKK + kk];
        float w1 = w[(size_t)(co*NC + c + 1)*NKK + kk];
        g_wAf[idx] = __floats2half2_rn(w0, w1);
    } else {
        int j = idx - NWA;
        if (j < NW27){
            int ch = j & 31, r = j >> 5;
            int stage = r >> 3, k2 = r & 7;
            int k = stage*16 + 2*k2;
            int kk = k >> 7, c = k & 127;
            float v0 = 0.f, v1 = 0.f;
            if (ch < 18){      v0 = ow[(size_t)(ch*NC + c)*NKK + kk];
                               v1 = ow[(size_t)(ch*NC + c + 1)*NKK + kk]; }
            else if (ch < 27){ v0 = mw[(size_t)((ch-18)*NC + c)*NKK + kk];
                               v1 = mw[(size_t)((ch-18)*NC + c + 1)*NKK + kk]; }
            g_w27h[j] = __floats2half2_rn(v0, v1);
        }
    }
}

// ---------------- conv27 (offsets + modulation) fp16 mma + meta build ------
// Block: 128 px x 32 ch. 256 threads, 8 warps x (32ch x 16px). 36 K32 stages.
#define C_AS 40
#define C_BS 136
#define OPAD 130
__global__ __launch_bounds__(256,2) void k_conv27(const float* __restrict__ off_b,
                                                  const float* __restrict__ mod_b){
    __shared__ __half2 A2c[2][16*C_AS];
    __shared__ __half2 B2c[2][16*C_BS];
    __shared__ float sOut[32][OPAD];

    const int b = blockIdx.y, p0 = blockIdx.x*128;
    const int t = threadIdx.x;
    const int wid = t>>5, lane = t&31;
    const int bpx = t>>2, bcq = t&3;
    const int arow = lane>>2, acol = lane&3;
    const int wn = wid*16;
    const __half* __restrict__ xb = g_xh + (size_t)b*NHW*NC;

    const __half* gp0 = xb; const __half* gp1 = xb;
    bool v0=false, v1=false;
    uint4 r0, r1;

    float acc[2][2][4];
#pragma unroll
    for (int i=0;i<2;i++)
#pragma unroll
        for (int j=0;j<2;j++)
#pragma unroll
            for (int q=0;q<4;q++) acc[i][j][q]=0.f;

    auto geom = [&](int kk){
        int ky = kk/3, kx = kk - ky*3;
#pragma unroll
        for (int i=0;i<2;i++){
            int p = p0 + bpx + 64*i;
            int h = p/96, w = p - h*96;
            int sy = h - 1 + ky, sx = w - 1 + kx;
            bool v = ((unsigned)sy < 96u) && ((unsigned)sx < 96u);
            const __half* gp = xb + (ptrdiff_t)(sy*96 + sx)*NC;
            if (i==0){ v0=v; gp0=gp; } else { v1=v; gp1=gp; }
        }
    };
    auto issue_a = [&](int s, int buf){
        if (t < 128){
            int row = t>>3, seg = t&7;
            unsigned d = su32(&A2c[buf][row*C_AS + seg*4]);
            const __half2* src = g_w27h + (size_t)(s*16 + row)*32 + seg*4;
            asm volatile("cp.async.cg.shared.global [%0], [%1], 16;\n" :: "r"(d), "l"(src));
        }
        asm volatile("cp.async.commit_group;\n");
    };
    auto issue_b = [&](int s){
        int c = (s&3)*32 + (bcq<<3);
        r0 = make_uint4(0u,0u,0u,0u);
        r1 = make_uint4(0u,0u,0u,0u);
        if (v0) r0 = *(const uint4*)(gp0 + c);
        if (v1) r1 = *(const uint4*)(gp1 + c);
    };
    auto store_b = [&](int buf){
        int xr = bcq<<3;
        const uint32_t* w0 = &r0.x;
        const uint32_t* w1 = &r1.x;
#pragma unroll
        for (int j=0;j<4;j++){
            int k2 = 4*bcq + j;
            *(uint32_t*)&B2c[buf][k2*C_BS + (bpx ^ xr)] = w0[j];
            *(uint32_t*)&B2c[buf][k2*C_BS + ((bpx+64) ^ xr)] = w1[j];
        }
    };

    geom(0);
    issue_a(0,0); issue_b(0); store_b(0);
    cpa_wait0();
    __syncthreads();

    for (int s=0;s<36;s++){
        int cur = s&1;
        if (s<35){
            issue_a(s+1, cur^1);
            if (((s+1)&3)==0) geom((s+1)>>2);
            issue_b(s+1);
        }
        const __half2* Ab = A2c[cur];
        const __half2* Bb = B2c[cur];
#pragma unroll
        for (int ks=0; ks<2; ks++){
            uint32_t a[2][4];
#pragma unroll
            for (int mt=0;mt<2;mt++){
                a[mt][0] = *(const uint32_t*)&Ab[(ks*8+acol)*C_AS + 16*mt + arow];
                a[mt][1] = *(const uint32_t*)&Ab[(ks*8+acol)*C_AS + 16*mt + arow + 8];
                a[mt][2] = *(const uint32_t*)&Ab[(ks*8+acol+4)*C_AS + 16*mt + arow];
                a[mt][3] = *(const uint32_t*)&Ab[(ks*8+acol+4)*C_AS + 16*mt + arow + 8];
            }
            int xr0 = ((ks*8+acol)>>2)<<3;
            int xr1 = ((ks*8+acol+4)>>2)<<3;
            uint32_t bq[2][2];
#pragma unroll
            for (int nt=0;nt<2;nt++){
                int pxn = wn + 8*nt + arow;
                bq[nt][0] = *(const uint32_t*)&Bb[(ks*8+acol)*C_BS + (pxn ^ xr0)];
                bq[nt][1] = *(const uint32_t*)&Bb[(ks*8+acol+4)*C_BS + (pxn ^ xr1)];
            }
#pragma unroll
            for (int mt=0;mt<2;mt++)
#pragma unroll
                for (int nt=0;nt<2;nt++)
                    mma_f16(acc[mt][nt], a[mt], bq[nt]);
        }

        if (s<35){
            store_b(cur^1);
            cpa_wait0();
        }
        __syncthreads();
    }

    // write conv output fragments to sOut
#pragma unroll
    for (int mt=0;mt<2;mt++)
#pragma unroll
        for (int nt=0;nt<2;nt++){
            int row = 16*mt + arow;
            int col = wn + 8*nt + 2*acol;
            float* cp = &sOut[row][col];
            cp[0] = acc[mt][nt][0]; cp[1] = acc[mt][nt][1];
            cp[8*OPAD] = acc[mt][nt][2]; cp[8*OPAD+1] = acc[mt][nt][3];
        }
    __syncthreads();

    if (t < 128){
        int p = p0 + t;
        int h = p/96, w = p - h*96;
#pragma unroll
        for (int kk=0; kk<9; kk++){
            float dy = sOut[2*kk  ][t] + off_b[2*kk];
            float dx = sOut[2*kk+1][t] + off_b[2*kk+1];
            float mp = sOut[18+kk][t] + mod_b[kk];
            float m  = 1.f/(1.f + expf(-mp));
            int ky = kk/3, kx = kk - ky*3;
            float py  = (float)(h - 1 + ky) + dy;
            float pxf = (float)(w - 1 + kx) + dx;
            float fy = floorf(py), fx = floorf(pxf);
            float ly = py - fy,  lx = pxf - fx;
            int y0 = (int)fy, x0 = (int)fx;
            int y1 = y0+1,   x1 = x0+1;
            bool vy0 = (unsigned)y0 < 96u, vy1 = (unsigned)y1 < 96u;
            bool vx0 = (unsigned)x0 < 96u, vx1 = (unsigned)x1 < 96u;
            float hy = 1.f - ly, hx = 1.f - lx;
            float w00 = (vy0&&vx0) ? hy*hx*m : 0.f;
            float w01 = (vy0&&vx1) ? hy*lx*m : 0.f;
            float w10 = (vy1&&vx0) ? ly*hx*m : 0.f;
            float w11 = (vy1&&vx1) ? ly*lx*m : 0.f;
            int cy0 = min(max(y0,0),95), cy1 = min(max(y1,0),95);
            int cx0 = min(max(x0,0),95), cx1 = min(max(x1,0),95);
            int i00 = (cy0*96+cx0)*NC, i01 = (cy0*96+cx1)*NC;
            int i10 = (cy1*96+cx0)*NC, i11 = (cy1*96+cx1)*NC;
            float* mo = &g_meta[((size_t)(b*NKK+kk)*NHW + p)*8];
            *(float4*)mo = make_float4(w00,w01,w10,w11);
            *(float4*)(mo+4) = make_float4(__int_as_float(i00), __int_as_float(i01),
                                           __int_as_float(i10), __int_as_float(i11));
        }
    }
}

// ---------------- main fused deformable GEMM: mma.sync fp16 ----------------
// Block tile: 256co x 128px, K=1152 in 36 chunks of 32 (16 k2 rows).
// 256 threads, 8 warps (4m x 2n), warp tile 64co x 64px.
// A: fragment-order smem (LDS.128), 2-stage cp.async pipeline.
// B: swizzled [k2][px] smem, 2-stage; bilinear combine in packed fp16.
#define CHUNKS 36
#define A2H2 4096                 // half2 per A buffer
#define B2S 136
#define B2BUF (16*B2S)            // 2176 half2
#define SMEM_PIPE_BYTES ((2*A2H2 + 2*B2BUF)*4)   // 50176
#define SMEM_EPI_BYTES (128*132*4)               // 67584

__global__ __launch_bounds__(256,1) void k_main_mma(const float* __restrict__ bias,
                                                    float* __restrict__ out){
    extern __shared__ char smraw[];
    __half2* A2 = (__half2*)smraw;              // [2][4096] fragment order
    __half2* B2 = A2 + 2*A2H2;                  // [2][16][B2S]
    float*   Cs = (float*)smraw;                // epilogue [128][132]

    const int t = threadIdx.x;
    const int wid = t>>5, lane = t&31;
    const int b = blockIdx.y, p0 = blockIdx.x*128;
    const __half* __restrict__ xb = g_xh + (size_t)b*NHW*NC;

    const int pxb = t>>2, q = t&3;
    const int wm4 = (wid&3)*4, wn = (wid>>2)*64;
    const int arow = lane>>2, acol = lane&3;

    __half2 hw0[4], hw1[4];      // bilinear weights broadcast to half2
    int4 mi0 = make_int4(0,0,0,0), mi1 = make_int4(0,0,0,0);
    uint4 gu[8];                 // raw gathered data
    __half2 rg[2][4];

    float acc[4][8][4];
#pragma unroll
    for (int i=0;i<4;i++)
#pragma unroll
        for (int j=0;j<8;j++)
#pragma unroll
            for (int qq=0;qq<4;qq++) acc[i][j][qq]=0.f;

    auto load_meta = [&](int kk){
        const float4* mp0 = (const float4*)&g_meta[((size_t)(b*NKK+kk)*NHW + p0 + pxb)*8];
        float4 mw0 = mp0[0];
        float4 ti = mp0[1];
        mi0.x = __float_as_int(ti.x); mi0.y = __float_as_int(ti.y);
        mi0.z = __float_as_int(ti.z); mi0.w = __float_as_int(ti.w);
        const float4* mp1 = (const float4*)&g_meta[((size_t)(b*NKK+kk)*NHW + p0 + pxb + 64)*8];
        float4 mw1 = mp1[0];
        float4 tj = mp1[1];
        mi1.x = __float_as_int(tj.x); mi1.y = __float_as_int(tj.y);
        mi1.z = __float_as_int(tj.z); mi1.w = __float_as_int(tj.w);
        hw0[0] = __float2half2_rn(mw0.x); hw0[1] = __float2half2_rn(mw0.y);
        hw0[2] = __float2half2_rn(mw0.z); hw0[3] = __float2half2_rn(mw0.w);
        hw1[0] = __float2half2_rn(mw1.x); hw1[1] = __float2half2_rn(mw1.y);
        hw1[2] = __float2half2_rn(mw1.z); hw1[3] = __float2half2_rn(mw1.w);
    };
    auto issue_a = [&](int chunk, int buf){
#pragma unroll
        for (int i=0;i<4;i++){
            int qq = t + 256*i;               // 0..1023, 16B each -> 16KB linear
            const __half2* src = g_wAf + (size_t)chunk*4096 + qq*4;
            unsigned dst = su32(A2 + buf*A2H2 + qq*4);
            asm volatile("cp.async.cg.shared.global [%0], [%1], 16;\n" :: "r"(dst), "l"(src));
        }
        asm volatile("cp.async.commit_group;\n");
    };
    auto gather_load = [&](int chunk){
        int csub = (chunk&3)*32 + q*8;
        gu[0] = *(const uint4*)(xb + mi0.x + csub);
        gu[1] = *(const uint4*)(xb + mi0.y + csub);
        gu[2] = *(const uint4*)(xb + mi0.z + csub);
        gu[3] = *(const uint4*)(xb + mi0.w + csub);
        gu[4] = *(const uint4*)(xb + mi1.x + csub);
        gu[5] = *(const uint4*)(xb + mi1.y + csub);
        gu[6] = *(const uint4*)(xb + mi1.z + csub);
        gu[7] = *(const uint4*)(xb + mi1.w + csub);
    };
    auto gather_combine = [&](){
#pragma unroll
        for (int e=0;e<2;e++){
            const __half2* hw = e ? hw1 : hw0;
            const uint32_t* p0v = &gu[4*e+0].x;
            const uint32_t* p1v = &gu[4*e+1].x;
            const uint32_t* p2v = &gu[4*e+2].x;
            const uint32_t* p3v = &gu[4*e+3].x;
#pragma unroll
            for (int j=0;j<4;j++){
                __half2 v = __hmul2(hw[0], *(const __half2*)&p0v[j]);
                v = __hfma2(hw[1], *(const __half2*)&p1v[j], v);
                v = __hfma2(hw[2], *(const __half2*)&p2v[j], v);
                v = __hfma2(hw[3], *(const __half2*)&p3v[j], v);
                rg[e][j] = v;
            }
        }
    };
    auto store_b = [&](int buf){
        int xr = ((q>>1)<<4) ^ ((q&1)<<3);
#pragma unroll
        for (int j=0;j<4;j++){
            int k2 = q*4 + j;
            B2[buf*B2BUF + k2*B2S + (pxb ^ xr)] = rg[0][j];
            B2[buf*B2BUF + k2*B2S + ((pxb+64) ^ xr)] = rg[1][j];
        }
    };

    // prologue
    load_meta(0);
    gather_load(0);
    issue_a(0, 0);
    gather_combine();
    store_b(0);
    cpa_wait0();
    __syncthreads();

    for (int chunk=0; chunk<CHUNKS; chunk++){
        const int cur = chunk&1;
        if (chunk < CHUNKS-1){
            if (((chunk+1)&3)==0) load_meta((chunk+1)>>2);
            gather_load(chunk+1);
            issue_a(chunk+1, cur^1);
        }

        const __half2* Ab = A2 + cur*A2H2;
        const __half2* Bb = B2 + cur*B2BUF;
#pragma unroll
        for (int ks=0; ks<2; ks++){
            uint32_t a[4][4];
#pragma unroll
            for (int mt=0;mt<4;mt++){
                uint4 av = *(const uint4*)(Ab + (ks*16 + wm4 + mt)*128 + lane*4);
                a[mt][0] = av.x; a[mt][1] = av.y; a[mt][2] = av.z; a[mt][3] = av.w;
            }
            uint32_t bq[8][2];
#pragma unroll
            for (int nt=0;nt<8;nt++){
                int pxn = (wn + 8*nt + arow) ^ (ks<<4);
                bq[nt][0] = *(const uint32_t*)&Bb[(ks*8+acol)*B2S + pxn];
                bq[nt][1] = *(const uint32_t*)&Bb[(ks*8+acol+4)*B2S + (pxn^8)];
            }
#pragma unroll
            for (int mt=0;mt<4;mt++)
#pragma unroll
                for (int nt=0;nt<8;nt++)
                    mma_f16(acc[mt][nt], a[mt], bq[nt]);
        }

        if (chunk < CHUNKS-1){
            gather_combine();
            store_b(cur^1);
            cpa_wait0();
        }
        __syncthreads();
    }

    // ---- epilogue: stage C through smem in 2 co-halves, coalesced + bias ----
#pragma unroll
    for (int h=0; h<2; h++){
        __syncthreads();
        if (((wid&3)>>1) == h){
            int rbase = (wid&3)*64 - 128*h;   // 0 or 64
#pragma unroll
            for (int mt=0;mt<4;mt++){
#pragma unroll
                for (int nt=0;nt<8;nt++){
                    int row = rbase + 16*mt + arow;
                    int col = wn + nt*8 + 2*acol;
                    float* cp2 = Cs + row*132 + col;
                    cp2[0] = acc[mt][nt][0]; cp2[1] = acc[mt][nt][1];
                    cp2[8*132] = acc[mt][nt][2]; cp2[8*132+1] = acc[mt][nt][3];
                }
            }
        }
        __syncthreads();
        {
            int r = t>>1, seg = (t&1)*64;
            int co = 128*h + r;
            float bz = __ldg(&bias[co]);
            float* op = out + (size_t)(b*NCO + co)*NHW + p0 + seg;
            const float* cr = Cs + r*132 + seg;
#pragma unroll
            for (int j=0;j<16;j++){
                float4 v = *(const float4*)(cr + j*4);
                v.x += bz; v.y += bz; v.z += bz; v.w += bz;
                *(float4*)(op + j*4) = v;
            }
        }
    }
}

// ---------------- launch ----------------
extern "C" void kernel_launch(void* const* d_in, const int* in_sizes, int n_in,
                              void* d_out, int out_size){
    (void)in_sizes; (void)n_in; (void)out_size;
    const float* x        = (const float*)d_in[0];
    const float* weight   = (const float*)d_in[1];
    const float* bias     = (const float*)d_in[2];
    const float* offset_w = (const float*)d_in[3];
    const float* offset_b = (const float*)d_in[4];
    const float* mod_w    = (const float*)d_in[5];
    const float* mod_b    = (const float*)d_in[6];
    float* out = (float*)d_out;

    const int SMEM_MAIN = (SMEM_PIPE_BYTES > SMEM_EPI_BYTES) ? SMEM_PIPE_BYTES : SMEM_EPI_BYTES;
    cudaFuncSetAttribute(k_main_mma, cudaFuncAttributeMaxDynamicSharedMemorySize, SMEM_MAIN);

    k_transpose<<<dim3(NHW/32, NC/32, NB), dim3(32,8)>>>(x);
    k_prep_all<<<(NWA + NW27 + 255)/256, 256>>>(weight, offset_w, mod_w);
    k_conv27<<<dim3(NHW/128, NB), 256>>>(offset_b, mod_b);
    k_main_mma<<<dim3(NHW/128, NB), 256, SMEM_MAIN>>>(bias, out);
}

// round 15
// speedup vs baseline: 1.1928x; 1.0469x over previous
#include <cuda_runtime.h>
#include <cuda_fp16.h>
#include <math.h>
#include <stddef.h>
#include <stdint.h>

#define NB 4
#define NC 128
#define NCO 256
#define NH 96
#define NW 96
#define NHW (NH*NW)          // 9216
#define NKK 9
#define NKDIM (NKK*NC)       // 1152

// ---- scratch (static device allocations) ----
__device__ __half  g_xh[(size_t)NB*NHW*NC];     // x as NHWC fp16 (9.4 MB)
__device__ __half2 g_wAf[36*4096];              // main weights, FRAGMENT order
__device__ __half2 g_w27h[72*8*32];             // conv27 weights [k2 global][ch]
__device__ float   g_meta[(size_t)NB*NKK*NHW*8];// per (b,kk,px): 4 weights + 4 indices

static __device__ __forceinline__ unsigned su32(const void* p){
    return (unsigned)__cvta_generic_to_shared(p);
}
static __device__ __forceinline__ void mma_f16(float* c, const uint32_t* a, const uint32_t* b){
    asm volatile("mma.sync.aligned.m16n8k16.row.col.f32.f16.f16.f32 "
        "{%0,%1,%2,%3}, {%4,%5,%6,%7}, {%8,%9}, {%0,%1,%2,%3};"
        : "+f"(c[0]), "+f"(c[1]), "+f"(c[2]), "+f"(c[3])
        : "r"(a[0]), "r"(a[1]), "r"(a[2]), "r"(a[3]), "r"(b[0]), "r"(b[1]));
}
static __device__ __forceinline__ void ldsm_x4(uint32_t* r, unsigned addr){
    asm volatile("ldmatrix.sync.aligned.m8n8.x4.shared.b16 {%0,%1,%2,%3}, [%4];"
        : "=r"(r[0]), "=r"(r[1]), "=r"(r[2]), "=r"(r[3]) : "r"(addr));
}
static __device__ __forceinline__ void cpa_wait0(){
    asm volatile("cp.async.wait_group 0;\n" ::: "memory");
}

// ---------------- transpose x: NCHW fp32 -> NHWC fp16 ----------------
__global__ void k_transpose(const float* __restrict__ x){
    __shared__ float tile[32][33];
    int b = blockIdx.z, c0 = blockIdx.y*32, p0 = blockIdx.x*32;
    int tx = threadIdx.x, ty = threadIdx.y;
    int t = ty*32 + tx;
#pragma unroll
    for (int i = ty; i < 32; i += 8)
        tile[i][tx] = x[((size_t)(b*NC + c0 + i))*NHW + p0 + tx];
    __syncthreads();
#pragma unroll
    for (int it = 0; it < 2; it++){
        int idx = it*256 + t;
        int p = idx >> 4, q = idx & 15;
        __half2 h = __floats2half2_rn(tile[2*q][p], tile[2*q+1][p]);
        *(__half2*)&g_xh[(size_t)(b*NHW + p0 + p)*NC + c0 + 2*q] = h;
    }
}

// ---------------- merged weight prep (main frag-order + conv27) -----------
#define NWA (36*4096)
#define NW27 (72*8*32)
__global__ void k_prep_all(const float* __restrict__ w,
                           const float* __restrict__ ow,
                           const float* __restrict__ mw){
    int idx = blockIdx.x*256 + threadIdx.x;
    if (idx < NWA){
        int chunk = idx >> 12;
        int rem   = idx & 4095;
        int ks    = rem >> 11;
        int mtg   = (rem >> 7) & 15;
        int lane  = (rem >> 2) & 31;
        int r     = rem & 3;
        int acol = lane & 3, arow = lane >> 2;
        int k2 = chunk*16 + ks*8 + acol + ((r>>1)<<2);
        int co = mtg*16 + arow + ((r&1)<<3);
        int k = 2*k2;
        int kk = k >> 7, c = k & 127;
        float w0 = w[(size_t)(co*NC + c)*NKK + kk];
        float w1 = w[(size_t)(co*NC + c + 1)*NKK + kk];
        g_wAf[idx] = __floats2half2_rn(w0, w1);
    } else {
        int j = idx - NWA;
        if (j < NW27){
            int ch = j & 31, r = j >> 5;
            int stage = r >> 3, k2 = r & 7;
            int k = stage*16 + 2*k2;
            int kk = k >> 7, c = k & 127;
            float v0 = 0.f, v1 = 0.f;
            if (ch < 18){      v0 = ow[(size_t)(ch*NC + c)*NKK + kk];
                               v1 = ow[(size_t)(ch*NC + c + 1)*NKK + kk]; }
            else if (ch < 27){ v0 = mw[(size_t)((ch-18)*NC + c)*NKK + kk];
                               v1 = mw[(size_t)((ch-18)*NC + c + 1)*NKK + kk]; }
            g_w27h[j] = __floats2half2_rn(v0, v1);
        }
    }
}

// ---------------- conv27 (offsets + modulation) fp16 mma + meta build ------
// Block: 128 px x 32 ch. 256 threads, 8 warps x (32ch x 16px). 36 K32 stages.
#define C_AS 40
#define C_BS 136
#define OPAD 130
__global__ __launch_bounds__(256,2) void k_conv27(const float* __restrict__ off_b,
                                                  const float* __restrict__ mod_b){
    __shared__ __half2 A2c[2][16*C_AS];
    __shared__ __half2 B2c[2][16*C_BS];
    __shared__ float sOut[32][OPAD];

    const int b = blockIdx.y, p0 = blockIdx.x*128;
    const int t = threadIdx.x;
    const int wid = t>>5, lane = t&31;
    const int bpx = t>>2, bcq = t&3;
    const int arow = lane>>2, acol = lane&3;
    const int wn = wid*16;
    const __half* __restrict__ xb = g_xh + (size_t)b*NHW*NC;

    const __half* gp0 = xb; const __half* gp1 = xb;
    bool v0=false, v1=false;
    uint4 r0, r1;

    float acc[2][2][4];
#pragma unroll
    for (int i=0;i<2;i++)
#pragma unroll
        for (int j=0;j<2;j++)
#pragma unroll
            for (int q=0;q<4;q++) acc[i][j][q]=0.f;

    auto geom = [&](int kk){
        int ky = kk/3, kx = kk - ky*3;
#pragma unroll
        for (int i=0;i<2;i++){
            int p = p0 + bpx + 64*i;
            int h = p/96, w = p - h*96;
            int sy = h - 1 + ky, sx = w - 1 + kx;
            bool v = ((unsigned)sy < 96u) && ((unsigned)sx < 96u);
            const __half* gp = xb + (ptrdiff_t)(sy*96 + sx)*NC;
            if (i==0){ v0=v; gp0=gp; } else { v1=v; gp1=gp; }
        }
    };
    auto issue_a = [&](int s, int buf){
        if (t < 128){
            int row = t>>3, seg = t&7;
            unsigned d = su32(&A2c[buf][row*C_AS + seg*4]);
            const __half2* src = g_w27h + (size_t)(s*16 + row)*32 + seg*4;
            asm volatile("cp.async.cg.shared.global [%0], [%1], 16;\n" :: "r"(d), "l"(src));
        }
        asm volatile("cp.async.commit_group;\n");
    };
    auto issue_b = [&](int s){
        int c = (s&3)*32 + (bcq<<3);
        r0 = make_uint4(0u,0u,0u,0u);
        r1 = make_uint4(0u,0u,0u,0u);
        if (v0) r0 = *(const uint4*)(gp0 + c);
        if (v1) r1 = *(const uint4*)(gp1 + c);
    };
    auto store_b = [&](int buf){
        int xr = bcq<<3;
        const uint32_t* w0 = &r0.x;
        const uint32_t* w1 = &r1.x;
#pragma unroll
        for (int j=0;j<4;j++){
            int k2 = 4*bcq + j;
            *(uint32_t*)&B2c[buf][k2*C_BS + (bpx ^ xr)] = w0[j];
            *(uint32_t*)&B2c[buf][k2*C_BS + ((bpx+64) ^ xr)] = w1[j];
        }
    };

    geom(0);
    issue_a(0,0); issue_b(0); store_b(0);
    cpa_wait0();
    __syncthreads();

    for (int s=0;s<36;s++){
        int cur = s&1;
        if (s<35){
            issue_a(s+1, cur^1);
            if (((s+1)&3)==0) geom((s+1)>>2);
            issue_b(s+1);
        }
        const __half2* Ab = A2c[cur];
        const __half2* Bb = B2c[cur];
#pragma unroll
        for (int ks=0; ks<2; ks++){
            uint32_t a[2][4];
#pragma unroll
            for (int mt=0;mt<2;mt++){
                a[mt][0] = *(const uint32_t*)&Ab[(ks*8+acol)*C_AS + 16*mt + arow];
                a[mt][1] = *(const uint32_t*)&Ab[(ks*8+acol)*C_AS + 16*mt + arow + 8];
                a[mt][2] = *(const uint32_t*)&Ab[(ks*8+acol+4)*C_AS + 16*mt + arow];
                a[mt][3] = *(const uint32_t*)&Ab[(ks*8+acol+4)*C_AS + 16*mt + arow + 8];
            }
            int xr0 = ((ks*8+acol)>>2)<<3;
            int xr1 = ((ks*8+acol+4)>>2)<<3;
            uint32_t bq[2][2];
#pragma unroll
            for (int nt=0;nt<2;nt++){
                int pxn = wn + 8*nt + arow;
                bq[nt][0] = *(const uint32_t*)&Bb[(ks*8+acol)*C_BS + (pxn ^ xr0)];
                bq[nt][1] = *(const uint32_t*)&Bb[(ks*8+acol+4)*C_BS + (pxn ^ xr1)];
            }
#pragma unroll
            for (int mt=0;mt<2;mt++)
#pragma unroll
                for (int nt=0;nt<2;nt++)
                    mma_f16(acc[mt][nt], a[mt], bq[nt]);
        }

        if (s<35){
            store_b(cur^1);
            cpa_wait0();
        }
        __syncthreads();
    }

    // write conv output fragments to sOut
#pragma unroll
    for (int mt=0;mt<2;mt++)
#pragma unroll
        for (int nt=0;nt<2;nt++){
            int row = 16*mt + arow;
            int col = wn + 8*nt + 2*acol;
            float* cp = &sOut[row][col];
            cp[0] = acc[mt][nt][0]; cp[1] = acc[mt][nt][1];
            cp[8*OPAD] = acc[mt][nt][2]; cp[8*OPAD+1] = acc[mt][nt][3];
        }
    __syncthreads();

    if (t < 128){
        int p = p0 + t;
        int h = p/96, w = p - h*96;
#pragma unroll
        for (int kk=0; kk<9; kk++){
            float dy = sOut[2*kk  ][t] + off_b[2*kk];
            float dx = sOut[2*kk+1][t] + off_b[2*kk+1];
            float mp = sOut[18+kk][t] + mod_b[kk];
            float m  = 1.f/(1.f + expf(-mp));
            int ky = kk/3, kx = kk - ky*3;
            float py  = (float)(h - 1 + ky) + dy;
            float pxf = (float)(w - 1 + kx) + dx;
            float fy = floorf(py), fx = floorf(pxf);
            float ly = py - fy,  lx = pxf - fx;
            int y0 = (int)fy, x0 = (int)fx;
            int y1 = y0+1,   x1 = x0+1;
            bool vy0 = (unsigned)y0 < 96u, vy1 = (unsigned)y1 < 96u;
            bool vx0 = (unsigned)x0 < 96u, vx1 = (unsigned)x1 < 96u;
            float hy = 1.f - ly, hx = 1.f - lx;
            float w00 = (vy0&&vx0) ? hy*hx*m : 0.f;
            float w01 = (vy0&&vx1) ? hy*lx*m : 0.f;
            float w10 = (vy1&&vx0) ? ly*hx*m : 0.f;
            float w11 = (vy1&&vx1) ? ly*lx*m : 0.f;
            int cy0 = min(max(y0,0),95), cy1 = min(max(y1,0),95);
            int cx0 = min(max(x0,0),95), cx1 = min(max(x1,0),95);
            int i00 = (cy0*96+cx0)*NC, i01 = (cy0*96+cx1)*NC;
            int i10 = (cy1*96+cx0)*NC, i11 = (cy1*96+cx1)*NC;
            float* mo = &g_meta[((size_t)(b*NKK+kk)*NHW + p)*8];
            *(float4*)mo = make_float4(w00,w01,w10,w11);
            *(float4*)(mo+4) = make_float4(__int_as_float(i00), __int_as_float(i01),
                                           __int_as_float(i10), __int_as_float(i11));
        }
    }
}

// ---------------- main fused deformable GEMM: mma.sync fp16 ----------------
// Block tile: 256co x 128px, K=1152 in 36 chunks of 32 (16 k2 rows).
// 256 threads, 8 warps (4m x 2n), warp tile 64co x 64px.
// A: fragment-order smem (LDS.128), 2-stage cp.async pipeline.
// B: px-major smem rows (stride 20 half2 = 80B, bank-perfect), builder
//    writes STS.128, reader uses ldmatrix.m8n8.x4 (8 per warp per chunk).
#define CHUNKS 36
#define A2H2 4096                 // half2 per A buffer
#define B2RS 20                   // half2 per px row (16 data + 4 pad)
#define B2BUF (128*B2RS)          // 2560 half2 per buffer
#define SMEM_PIPE_BYTES ((2*A2H2 + 2*B2BUF)*4)   // 53248
#define SMEM_EPI_BYTES (128*132*4)               // 67584

__global__ __launch_bounds__(256,1) void k_main_mma(const float* __restrict__ bias,
                                                    float* __restrict__ out){
    extern __shared__ char smraw[];
    __half2* A2 = (__half2*)smraw;              // [2][4096] fragment order
    __half2* B2 = A2 + 2*A2H2;                  // [2][128][B2RS] px-major
    float*   Cs = (float*)smraw;                // epilogue [128][132]

    const int t = threadIdx.x;
    const int wid = t>>5, lane = t&31;
    const int b = blockIdx.y, p0 = blockIdx.x*128;
    const __half* __restrict__ xb = g_xh + (size_t)b*NHW*NC;

    const int pxb = t>>2, q = t&3;
    const int wm4 = (wid&3)*4, wn = (wid>>2)*64;
    const int arow = lane>>2, acol = lane&3;

    __half2 hw0[4], hw1[4];      // bilinear weights broadcast to half2
    int4 mi0 = make_int4(0,0,0,0), mi1 = make_int4(0,0,0,0);
    uint4 gu[8];                 // raw gathered data
    __half2 rg[2][4];

    // ldmatrix lane geometry: matrix m = lane>>3, row r = lane&7
    const int lm_m = lane>>3, lm_r = lane&7;
    const int lm_nth = lm_m>>1, lm_qd = lm_m&1;   // nt offset within pair, qd

    float acc[4][8][4];
#pragma unroll
    for (int i=0;i<4;i++)
#pragma unroll
        for (int j=0;j<8;j++)
#pragma unroll
            for (int qq=0;qq<4;qq++) acc[i][j][qq]=0.f;

    auto load_meta = [&](int kk){
        const float4* mp0 = (const float4*)&g_meta[((size_t)(b*NKK+kk)*NHW + p0 + pxb)*8];
        float4 mw0 = mp0[0];
        float4 ti = mp0[1];
        mi0.x = __float_as_int(ti.x); mi0.y = __float_as_int(ti.y);
        mi0.z = __float_as_int(ti.z); mi0.w = __float_as_int(ti.w);
        const float4* mp1 = (const float4*)&g_meta[((size_t)(b*NKK+kk)*NHW + p0 + pxb + 64)*8];
        float4 mw1 = mp1[0];
        float4 tj = mp1[1];
        mi1.x = __float_as_int(tj.x); mi1.y = __float_as_int(tj.y);
        mi1.z = __float_as_int(tj.z); mi1.w = __float_as_int(tj.w);
        hw0[0] = __float2half2_rn(mw0.x); hw0[1] = __float2half2_rn(mw0.y);
        hw0[2] = __float2half2_rn(mw0.z); hw0[3] = __float2half2_rn(mw0.w);
        hw1[0] = __float2half2_rn(mw1.x); hw1[1] = __float2half2_rn(mw1.y);
        hw1[2] = __float2half2_rn(mw1.z); hw1[3] = __float2half2_rn(mw1.w);
    };
    auto issue_a = [&](int chunk, int buf){
#pragma unroll
        for (int i=0;i<4;i++){
            int qq = t + 256*i;               // 0..1023, 16B each -> 16KB linear
            const __half2* src = g_wAf + (size_t)chunk*4096 + qq*4;
            unsigned dst = su32(A2 + buf*A2H2 + qq*4);
            asm volatile("cp.async.cg.shared.global [%0], [%1], 16;\n" :: "r"(dst), "l"(src));
        }
        asm volatile("cp.async.commit_group;\n");
    };
    auto gather_load = [&](int chunk){
        int csub = (chunk&3)*32 + q*8;
        gu[0] = *(const uint4*)(xb + mi0.x + csub);
        gu[1] = *(const uint4*)(xb + mi0.y + csub);
        gu[2] = *(const uint4*)(xb + mi0.z + csub);
        gu[3] = *(const uint4*)(xb + mi0.w + csub);
        gu[4] = *(const uint4*)(xb + mi1.x + csub);
        gu[5] = *(const uint4*)(xb + mi1.y + csub);
        gu[6] = *(const uint4*)(xb + mi1.z + csub);
        gu[7] = *(const uint4*)(xb + mi1.w + csub);
    };
    auto gather_combine = [&](){
#pragma unroll
        for (int e=0;e<2;e++){
            const __half2* hw = e ? hw1 : hw0;
            const uint32_t* p0v = &gu[4*e+0].x;
            const uint32_t* p1v = &gu[4*e+1].x;
            const uint32_t* p2v = &gu[4*e+2].x;
            const uint32_t* p3v = &gu[4*e+3].x;
#pragma unroll
            for (int j=0;j<4;j++){
                __half2 v = __hmul2(hw[0], *(const __half2*)&p0v[j]);
                v = __hfma2(hw[1], *(const __half2*)&p1v[j], v);
                v = __hfma2(hw[2], *(const __half2*)&p2v[j], v);
                v = __hfma2(hw[3], *(const __half2*)&p3v[j], v);
                rg[e][j] = v;
            }
        }
    };
    // px-major store: one STS.128 per px-region (k2c = q*4..q*4+3)
    auto store_b = [&](int buf){
        __half2* bp = B2 + buf*B2BUF;
        *(uint4*)&bp[pxb*B2RS + q*4]      = *(const uint4*)&rg[0][0];
        *(uint4*)&bp[(pxb+64)*B2RS + q*4] = *(const uint4*)&rg[1][0];
    };

    // prologue
    load_meta(0);
    gather_load(0);
    issue_a(0, 0);
    gather_combine();
    store_b(0);
    cpa_wait0();
    __syncthreads();

    for (int chunk=0; chunk<CHUNKS; chunk++){
        const int cur = chunk&1;
        if (chunk < CHUNKS-1){
            if (((chunk+1)&3)==0) load_meta((chunk+1)>>2);
            gather_load(chunk+1);
            issue_a(chunk+1, cur^1);
        }

        const __half2* Ab = A2 + cur*A2H2;
        const unsigned bbase = su32(B2 + cur*B2BUF);
#pragma unroll
        for (int ks=0; ks<2; ks++){
            uint32_t a[4][4];
#pragma unroll
            for (int mt=0;mt<4;mt++){
                uint4 av = *(const uint4*)(Ab + (ks*16 + wm4 + mt)*128 + lane*4);
                a[mt][0] = av.x; a[mt][1] = av.y; a[mt][2] = av.z; a[mt][3] = av.w;
            }
            uint32_t bq[8][2];
#pragma unroll
            for (int g=0; g<4; g++){
                int nt = 2*g + lm_nth;
                unsigned addr = bbase +
                    ((unsigned)((wn + 8*nt + lm_r)*B2RS + ks*8 + lm_qd*4) << 2);
                uint32_t rr[4];
                ldsm_x4(rr, addr);
                bq[2*g][0]   = rr[0];
                bq[2*g][1]   = rr[1];
                bq[2*g+1][0] = rr[2];
                bq[2*g+1][1] = rr[3];
            }
#pragma unroll
            for (int mt=0;mt<4;mt++)
#pragma unroll
                for (int nt=0;nt<8;nt++)
                    mma_f16(acc[mt][nt], a[mt], bq[nt]);
        }

        if (chunk < CHUNKS-1){
            gather_combine();
            store_b(cur^1);
            cpa_wait0();
        }
        __syncthreads();
    }

    // ---- epilogue: stage C through smem in 2 co-halves, coalesced + bias ----
#pragma unroll
    for (int h=0; h<2; h++){
        __syncthreads();
        if (((wid&3)>>1) == h){
            int rbase = (wid&3)*64 - 128*h;   // 0 or 64
#pragma unroll
            for (int mt=0;mt<4;mt++){
#pragma unroll
                for (int nt=0;nt<8;nt++){
                    int row = rbase + 16*mt + arow;
                    int col = wn + nt*8 + 2*acol;
                    float* cp2 = Cs + row*132 + col;
                    cp2[0] = acc[mt][nt][0]; cp2[1] = acc[mt][nt][1];
                    cp2[8*132] = acc[mt][nt][2]; cp2[8*132+1] = acc[mt][nt][3];
                }
            }
        }
        __syncthreads();
        {
            int r = t>>1, seg = (t&1)*64;
            int co = 128*h + r;
            float bz = __ldg(&bias[co]);
            float* op = out + (size_t)(b*NCO + co)*NHW + p0 + seg;
            const float* cr = Cs + r*132 + seg;
#pragma unroll
            for (int j=0;j<16;j++){
                float4 v = *(const float4*)(cr + j*4);
                v.x += bz; v.y += bz; v.z += bz; v.w += bz;
                *(float4*)(op + j*4) = v;
            }
        }
    }
}

// ---------------- launch ----------------
extern "C" void kernel_launch(void* const* d_in, const int* in_sizes, int n_in,
                              void* d_out, int out_size){
    (void)in_sizes; (void)n_in; (void)out_size;
    const float* x        = (const float*)d_in[0];
    const float* weight   = (const float*)d_in[1];
    const float* bias     = (const float*)d_in[2];
    const float* offset_w = (const float*)d_in[3];
    const float* offset_b = (const float*)d_in[4];
    const float* mod_w    = (const float*)d_in[5];
    const float* mod_b    = (const float*)d_in[6];
    float* out = (float*)d_out;

    const int SMEM_MAIN = (SMEM_PIPE_BYTES > SMEM_EPI_BYTES) ? SMEM_PIPE_BYTES : SMEM_EPI_BYTES;
    cudaFuncSetAttribute(k_main_mma, cudaFuncAttributeMaxDynamicSharedMemorySize, SMEM_MAIN);

    k_transpose<<<dim3(NHW/32, NC/32, NB), dim3(32,8)>>>(x);
    k_prep_all<<<(NWA + NW27 + 255)/256, 256>>>(weight, offset_w, mod_w);
    k_conv27<<<dim3(NHW/128, NB), 256>>>(offset_b, mod_b);
    k_main_mma<<<dim3(NHW/128, NB), 256, SMEM_MAIN>>>(bias, out);
}